// round 8
// baseline (speedup 1.0000x reference)
#include <cuda_runtime.h>
#include <cstdint>

// Problem dims
#define BB 4
#define TT 64
#define NN 16
#define MM 8
#define DD 512
#define ROWS (BB * TT * NN * MM)   // 32768
#define TNM  (TT * NN * MM)

// ---------------------------------------------------------------------------
// Scratch (__device__ globals)
// ---------------------------------------------------------------------------
__device__ float g_Q[(size_t)ROWS * DD];
__device__ float g_K[(size_t)ROWS * DD];
__device__ float g_V[(size_t)ROWS * DD];
__device__ float g_W[TT * NN * MM * MM];

__device__ __align__(16) int8_t g_x1[(size_t)ROWS * DD];
__device__ __align__(16) int8_t g_x2[(size_t)ROWS * DD];
__device__ __align__(16) int8_t g_w1[3 * DD * DD];
__device__ __align__(16) int8_t g_w2[3 * DD * DD];

// Fixed-point split constants: x ~ N(0,1) range +-6.35; W ~ N(0,1/512) range +-0.254
#define A1Q   20.0f
#define INV_A1 (1.0f / 20.0f)
#define A2Q   5080.0f                 // 254 * A1
#define INV_A2 (INV_A1 / 254.0f)
#define B1Q   500.0f
#define INV_B1 (1.0f / 500.0f)
#define B2Q   127000.0f               // 254 * B1
#define INV_B2 (INV_B1 / 254.0f)
#define S11F  (INV_A1 * INV_B1)
#define S12F  (INV_A1 * INV_B2)       // == INV_A2*INV_B1
#define S22F  (INV_A2 * INV_B2)

// ---------------------------------------------------------------------------
// Helpers
// ---------------------------------------------------------------------------
__device__ __forceinline__ uint32_t smem_to_u32(const void* smem_ptr) {
    uint32_t addr;
    asm("{ .reg .u64 tmp; cvta.to.shared.u64 tmp, %1; cvt.u32.u64 %0, tmp; }"
        : "=r"(addr) : "l"(smem_ptr));
    return addr;
}

__device__ __forceinline__ void cp_async16(uint32_t dst, const void* src) {
    asm volatile("cp.async.cg.shared.global [%0], [%1], 16;"
                 :: "r"(dst), "l"(src) : "memory");
}
__device__ __forceinline__ void cp_commit() {
    asm volatile("cp.async.commit_group;" ::: "memory");
}
__device__ __forceinline__ void cp_wait3() {
    asm volatile("cp.async.wait_group 3;" ::: "memory");
}

__device__ __forceinline__ void ldmatrix_x4(
    uint32_t& r0, uint32_t& r1, uint32_t& r2, uint32_t& r3, uint32_t addr)
{
    asm volatile("ldmatrix.sync.aligned.m8n8.x4.shared.b16 {%0,%1,%2,%3}, [%4];"
                 : "=r"(r0), "=r"(r1), "=r"(r2), "=r"(r3) : "r"(addr));
}

__device__ __forceinline__ void imma_16832(
    int& c0, int& c1, int& c2, int& c3,
    uint32_t a0, uint32_t a1, uint32_t a2, uint32_t a3,
    uint32_t b0, uint32_t b1)
{
    asm volatile(
        "mma.sync.aligned.m16n8k32.row.col.s32.s8.s8.s32 "
        "{%0,%1,%2,%3}, {%4,%5,%6,%7}, {%8,%9}, {%0,%1,%2,%3};"
        : "+r"(c0), "+r"(c1), "+r"(c2), "+r"(c3)
        : "r"(a0), "r"(a1), "r"(a2), "r"(a3), "r"(b0), "r"(b1));
}

// int8 SMEM layout: row r of 32B; 16B-half kh swizzled: kh' = kh ^ ((r>>2)&1)
__device__ __forceinline__ uint32_t swz32(int r, int kh) {
    return (uint32_t)(r * 32 + ((kh ^ ((r >> 2) & 1)) << 4));
}

// ---------------------------------------------------------------------------
// Quantize kernels: fp32 -> two-level int8
// ---------------------------------------------------------------------------
__device__ __forceinline__ void quant2(float v, float aq, float inv_a, float a2q,
                                       int& h, int& l) {
    float c1 = fminf(127.0f, fmaxf(-127.0f, rintf(v * aq)));
    float r  = v - c1 * inv_a;
    float c2 = fminf(127.0f, fmaxf(-127.0f, rintf(r * a2q)));
    h = (int)c1; l = (int)c2;
}

__device__ __forceinline__ uint32_t pack4(int b0, int b1, int b2, int b3) {
    return (uint32_t)(b0 & 0xFF) | ((uint32_t)(b1 & 0xFF) << 8) |
           ((uint32_t)(b2 & 0xFF) << 16) | ((uint32_t)(b3 & 0xFF) << 24);
}

__global__ __launch_bounds__(256) void convert_x(const float* __restrict__ x)
{
    size_t i = (size_t)blockIdx.x * 256 + threadIdx.x;
    float4 v = ((const float4*)x)[i];
    int h0, l0, h1, l1, h2, l2, h3, l3;
    quant2(v.x, A1Q, INV_A1, A2Q, h0, l0);
    quant2(v.y, A1Q, INV_A1, A2Q, h1, l1);
    quant2(v.z, A1Q, INV_A1, A2Q, h2, l2);
    quant2(v.w, A1Q, INV_A1, A2Q, h3, l3);
    ((uint32_t*)g_x1)[i] = pack4(h0, h1, h2, h3);
    ((uint32_t*)g_x2)[i] = pack4(l0, l1, l2, l3);
}

__global__ __launch_bounds__(256) void convert_w(
    const float* __restrict__ Wq, const float* __restrict__ Wk, const float* __restrict__ Wv)
{
    const float* W = (blockIdx.y == 0) ? Wq : (blockIdx.y == 1) ? Wk : Wv;
    size_t base = (size_t)blockIdx.y * (DD * DD / 4);
    size_t i = (size_t)blockIdx.x * 256 + threadIdx.x;
    float4 v = ((const float4*)W)[i];
    int h0, l0, h1, l1, h2, l2, h3, l3;
    quant2(v.x, B1Q, INV_B1, B2Q, h0, l0);
    quant2(v.y, B1Q, INV_B1, B2Q, h1, l1);
    quant2(v.z, B1Q, INV_B1, B2Q, h2, l2);
    quant2(v.w, B1Q, INV_B1, B2Q, h3, l3);
    ((uint32_t*)g_w1)[base + i] = pack4(h0, h1, h2, h3);
    ((uint32_t*)g_w2)[base + i] = pack4(l0, l1, l2, l3);
}

// ---------------------------------------------------------------------------
// QKV projection GEMM via int8 mma.sync m16n8k32 (two-level fixed point).
// Q = S11*(X1W1) + S12*(X1W2 + X2W1) + S22*(X2W2), s32 accs, fp32 masters.
// CTA 128x128, 8 warps (2m x 4n), warp tile 64x32.
// 64 virtual k32-chunks = 4 terms x 16; cp.async, 4 groups of 2 chunks in flight.
// grid = (4 n, 256 m, 3 z), 256 threads.
// ---------------------------------------------------------------------------
#define GROUP_BYTES 16384u    // 2 chunks x (A 4KB + B 4KB)
#define SMEM_DYN (4 * GROUP_BYTES + 1024)

__global__ __launch_bounds__(256, 1) void qkv_imma(
    const float* __restrict__ bq, const float* __restrict__ bk, const float* __restrict__ bv)
{
    extern __shared__ __align__(16) char dsm[];
    const uint32_t raw  = smem_to_u32(dsm);
    const uint32_t base = (raw + 1023u) & ~1023u;

    const int tid  = threadIdx.x;
    const int wid  = tid >> 5;
    const int lane = tid & 31;
    const int wm   = wid & 1;
    const int wn   = wid >> 1;        // 0..3

    const int z    = blockIdx.z;
    const int row0 = blockIdx.y * 128;
    const int col0 = blockIdx.x * 128;

    const int8_t* w1z = g_w1 + (size_t)z * (DD * DD);
    const int8_t* w2z = g_w2 + (size_t)z * (DD * DD);

    // ldmatrix per-lane offsets (relative to chunk base)
    // A frag: row = wm*64 + mf*16 + (lane&15), kh = lane>>4; mf advances +512
    uint32_t aoff;
    { int r = wm * 64 + (lane & 15); int kh = lane >> 4; aoff = swz32(r, kh); }
    // B frag: n = wn*32 + (lane&7) + ((lane>>4)&1)*8, kh = (lane>>3)&1; +4096 B area
    uint32_t boff;
    { int n = wn * 32 + (lane & 7) + ((lane >> 4) & 1) * 8; int kh = (lane >> 3) & 1;
      boff = swz32(n, kh) + 4096u; }

    // loader mapping: 256 threads: r = tid>>1 (0..127), kh = tid&1
    const int lr  = tid >> 1;
    const int lkh = tid & 1;
    const uint32_t sA = swz32(lr, lkh);
    const uint32_t sB = sA + 4096u;

    int   acc[4][4][4];
    float mst[4][4][4];
#pragma unroll
    for (int mf = 0; mf < 4; mf++)
#pragma unroll
        for (int nf = 0; nf < 4; nf++)
#pragma unroll
            for (int q = 0; q < 4; q++) { acc[mf][nf][q] = 0; mst[mf][nf][q] = 0.0f; }

    auto issue_group = [&](int g) {
#pragma unroll
        for (int cc = 0; cc < 2; cc++) {
            const int vc = 2 * g + cc;
            const int t  = vc >> 4;
            const int kb = (vc & 15) * 32 + lkh * 16;
            const int8_t* As = (t < 2) ? g_x1 : g_x2;
            const int8_t* Bs = (t & 1) ? w2z : w1z;
            const uint32_t st = base + (uint32_t)(g & 3) * GROUP_BYTES + (uint32_t)cc * 8192u;
            cp_async16(st + sA, As + (size_t)(row0 + lr) * DD + kb);
            cp_async16(st + sB, Bs + (size_t)(col0 + lr) * DD + kb);
        }
    };

    issue_group(0); cp_commit();
    issue_group(1); cp_commit();
    issue_group(2); cp_commit();

    for (int g = 0; g < 32; g++) {
        if (g + 3 < 32) issue_group(g + 3);
        cp_commit();                    // one group per iteration, possibly empty
        cp_wait3();
        __syncthreads();

        const uint32_t gb = base + (uint32_t)(g & 3) * GROUP_BYTES;
#pragma unroll
        for (int cc = 0; cc < 2; cc++) {
            const uint32_t ab = gb + (uint32_t)cc * 8192u;
            uint32_t a[4][4];
#pragma unroll
            for (int mf = 0; mf < 4; mf++)
                ldmatrix_x4(a[mf][0], a[mf][1], a[mf][2], a[mf][3],
                            ab + aoff + (uint32_t)mf * 512u);
            uint32_t b[4][2];
            {
                uint32_t r0, r1, r2, r3;
                ldmatrix_x4(r0, r1, r2, r3, ab + boff);
                b[0][0] = r0; b[0][1] = r1; b[1][0] = r2; b[1][1] = r3;
                ldmatrix_x4(r0, r1, r2, r3, ab + boff + 512u);
                b[2][0] = r0; b[2][1] = r1; b[3][0] = r2; b[3][1] = r3;
            }
#pragma unroll
            for (int mf = 0; mf < 4; mf++)
#pragma unroll
                for (int nf = 0; nf < 4; nf++)
                    imma_16832(acc[mf][nf][0], acc[mf][nf][1], acc[mf][nf][2], acc[mf][nf][3],
                               a[mf][0], a[mf][1], a[mf][2], a[mf][3],
                               b[nf][0], b[nf][1]);
        }

        if ((g & 7) == 7) {             // end of a term (16 chunks)
            const int t = g >> 3;
            const float ts = (t == 0) ? S11F : (t == 3) ? S22F : S12F;
#pragma unroll
            for (int mf = 0; mf < 4; mf++)
#pragma unroll
                for (int nf = 0; nf < 4; nf++)
#pragma unroll
                    for (int q = 0; q < 4; q++) {
                        mst[mf][nf][q] = fmaf(ts, (float)acc[mf][nf][q], mst[mf][nf][q]);
                        acc[mf][nf][q] = 0;
                    }
        }
        __syncthreads();
    }

    float* out = (z == 0) ? g_Q : (z == 1) ? g_K : g_V;
    const float* bias = (z == 0) ? bq : (z == 1) ? bk : bv;

#pragma unroll
    for (int nf = 0; nf < 4; nf++) {
        const int col = col0 + wn * 32 + nf * 8 + (lane & 3) * 2;
        float2 bb = *(const float2*)(bias + col);
#pragma unroll
        for (int mf = 0; mf < 4; mf++) {
            const int r0 = row0 + wm * 64 + mf * 16 + (lane >> 2);
            float2 v0 = make_float2(mst[mf][nf][0] + bb.x, mst[mf][nf][1] + bb.y);
            float2 v1 = make_float2(mst[mf][nf][2] + bb.x, mst[mf][nf][3] + bb.y);
            *(float2*)(out + (size_t)r0 * DD + col)       = v0;
            *(float2*)(out + (size_t)(r0 + 8) * DD + col) = v1;
        }
    }
}

// ---------------------------------------------------------------------------
// Kernel 2: attention scores + softmax (unchanged from R7, passing)
// ---------------------------------------------------------------------------
__global__ __launch_bounds__(256) void score_softmax()
{
    __shared__ float sQ[4096];
    __shared__ float sK[4096];
    __shared__ float part[64 * 65];
    __shared__ float sc[64];
    __shared__ float es[64];

    const int tn  = blockIdx.x;
    const int tid = threadIdx.x;
    const int b    = tid >> 6;
    const int r    = tid & 63;
    const int tile = r >> 4;
    const int slc  = r & 15;
    const int mt   = tile >> 1;
    const int kt   = tile & 1;

    float acc[4][4];
#pragma unroll
    for (int i = 0; i < 4; i++)
#pragma unroll
        for (int j = 0; j < 4; j++) acc[i][j] = 0.0f;

    const float4* Q4 = (const float4*)g_Q;
    const float4* K4 = (const float4*)g_K;

    for (int ch = 0; ch < 4; ch++) {
        __syncthreads();
#pragma unroll
        for (int j = 0; j < 4; j++) {
            int idx = tid + j * 256;
            int lb = idx >> 8, lrr = (idx >> 5) & 7, o = idx & 31;
            size_t grow = (size_t)lb * TNM + (size_t)tn * MM + lrr;
            ((float4*)sQ)[(lb * 8 + lrr) * 32 + o] = Q4[grow * (DD / 4) + ch * 32 + o];
            ((float4*)sK)[(lb * 8 + lrr) * 32 + o] = K4[grow * (DD / 4) + ch * 32 + o];
        }
        __syncthreads();

#pragma unroll
        for (int j = 0; j < 2; j++) {
            const int d4 = j * 16 + slc;
            float4 qf[4], kf[4];
#pragma unroll
            for (int i = 0; i < 4; i++)
                qf[i] = ((const float4*)sQ)[(b * 8 + mt * 4 + i) * 32 + d4];
#pragma unroll
            for (int i = 0; i < 4; i++)
                kf[i] = ((const float4*)sK)[(b * 8 + kt * 4 + i) * 32 + d4];
#pragma unroll
            for (int i = 0; i < 4; i++)
#pragma unroll
                for (int kx = 0; kx < 4; kx++) {
                    acc[i][kx] = fmaf(qf[i].x, kf[kx].x, acc[i][kx]);
                    acc[i][kx] = fmaf(qf[i].y, kf[kx].y, acc[i][kx]);
                    acc[i][kx] = fmaf(qf[i].z, kf[kx].z, acc[i][kx]);
                    acc[i][kx] = fmaf(qf[i].w, kf[kx].w, acc[i][kx]);
                }
        }
    }

    const int h = b * 16 + slc;
#pragma unroll
    for (int i = 0; i < 4; i++)
#pragma unroll
        for (int kx = 0; kx < 4; kx++) {
            int pair = (mt * 4 + i) * 8 + (kt * 4 + kx);
            part[h * 65 + pair] = acc[i][kx];
        }
    __syncthreads();

    if (tid < 64) {
        float s = 0.0f;
#pragma unroll
        for (int i = 0; i < 64; i++) s += part[i * 65 + tid];
        sc[tid] = s * 0.04419417382415922f;
    }
    __syncthreads();

    if (tid < 64) {
        const int m = tid >> 3;
        float mx = sc[m * 8];
#pragma unroll
        for (int j = 1; j < 8; j++) mx = fmaxf(mx, sc[m * 8 + j]);
        es[tid] = expf(sc[tid] - mx);
    }
    __syncthreads();

    if (tid < 64) {
        const int m = tid >> 3;
        float sum = 0.0f;
#pragma unroll
        for (int j = 0; j < 8; j++) sum += es[m * 8 + j];
        g_W[tn * 64 + tid] = es[tid] / sum;
    }
}

// ---------------------------------------------------------------------------
// Kernel 3: weighted V sum (unchanged)
// ---------------------------------------------------------------------------
__global__ __launch_bounds__(256) void out_kernel(float* __restrict__ out)
{
    const int btn = blockIdx.x;
    const int tid = threadIdx.x;
    const int d4  = tid & 127;
    const int mh  = tid >> 7;
    const int tn  = btn % (TT * NN);

    __shared__ float w[64];
    if (tid < 64) w[tid] = g_W[tn * 64 + tid];
    __syncthreads();

    const float4* V4 = (const float4*)(g_V + (size_t)btn * MM * DD);
    float4* O4 = (float4*)(out + (size_t)btn * MM * DD);

    float4 acc[4];
#pragma unroll
    for (int i = 0; i < 4; i++) acc[i] = make_float4(0.f, 0.f, 0.f, 0.f);

#pragma unroll
    for (int k = 0; k < 8; k++) {
        float4 v = V4[k * (DD / 4) + d4];
#pragma unroll
        for (int i = 0; i < 4; i++) {
            float wm = w[(mh * 4 + i) * 8 + k];
            acc[i].x = fmaf(wm, v.x, acc[i].x);
            acc[i].y = fmaf(wm, v.y, acc[i].y);
            acc[i].z = fmaf(wm, v.z, acc[i].z);
            acc[i].w = fmaf(wm, v.w, acc[i].w);
        }
    }

#pragma unroll
    for (int i = 0; i < 4; i++) {
        O4[(mh * 4 + i) * (DD / 4) + d4] = acc[i];
    }
}

// ---------------------------------------------------------------------------
extern "C" void kernel_launch(void* const* d_in, const int* in_sizes, int n_in,
                              void* d_out, int out_size)
{
    const float* x  = (const float*)d_in[0];
    const float* Wq = (const float*)d_in[1];
    const float* bq = (const float*)d_in[2];
    const float* Wk = (const float*)d_in[3];
    const float* bk = (const float*)d_in[4];
    const float* Wv = (const float*)d_in[5];
    const float* bv = (const float*)d_in[6];

    cudaFuncSetAttribute(qkv_imma, cudaFuncAttributeMaxDynamicSharedMemorySize, SMEM_DYN);

    convert_x<<<(ROWS * DD / 4) / 256, 256>>>(x);
    convert_w<<<dim3((DD * DD / 4) / 256, 3), 256>>>(Wq, Wk, Wv);
    qkv_imma<<<dim3(4, ROWS / 128, 3), 256, SMEM_DYN>>>(bq, bk, bv);
    score_softmax<<<TT * NN, 256>>>();
    out_kernel<<<BB * TT * NN, 256>>>((float*)d_out);
}

// round 9
// speedup vs baseline: 3.3848x; 3.3848x over previous
#include <cuda_runtime.h>
#include <cuda_bf16.h>
#include <cstdint>

// Problem dims
#define BB 4
#define TT 64
#define NN 16
#define MM 8
#define DD 512
#define ROWS (BB * TT * NN * MM)   // 32768 flattened (b,t,n,m) rows
#define TNM  (TT * NN * MM)

// ---------------------------------------------------------------------------
// Scratch (__device__ globals; allocation-free rule)
// ---------------------------------------------------------------------------
__device__ float g_Q[(size_t)ROWS * DD];
__device__ float g_K[(size_t)ROWS * DD];
__device__ float g_V[(size_t)ROWS * DD];
__device__ float g_W[TT * NN * MM * MM];

__device__ __align__(16) __nv_bfloat16 g_xh[(size_t)ROWS * DD];
__device__ __align__(16) __nv_bfloat16 g_xl[(size_t)ROWS * DD];
__device__ __align__(16) __nv_bfloat16 g_wh[3 * DD * DD];
__device__ __align__(16) __nv_bfloat16 g_wl[3 * DD * DD];

// ---------------------------------------------------------------------------
// Helpers
// ---------------------------------------------------------------------------
__device__ __forceinline__ uint32_t smem_to_u32(const void* smem_ptr) {
    uint32_t addr;
    asm("{ .reg .u64 tmp; cvta.to.shared.u64 tmp, %1; cvt.u32.u64 %0, tmp; }"
        : "=r"(addr) : "l"(smem_ptr));
    return addr;
}

#define SMEM_SWIZZLE_128B(byte_offset) \
    ((byte_offset) ^ (((byte_offset) >> 3) & 0x70))

__device__ __forceinline__ void cp_async16(uint32_t dst, const void* src) {
    asm volatile("cp.async.cg.shared.global [%0], [%1], 16;"
                 :: "r"(dst), "l"(src) : "memory");
}
__device__ __forceinline__ void cp_commit() {
    asm volatile("cp.async.commit_group;" ::: "memory");
}
__device__ __forceinline__ void cp_wait1() {
    asm volatile("cp.async.wait_group 1;" ::: "memory");
}
__device__ __forceinline__ void cp_wait0() {
    asm volatile("cp.async.wait_group 0;" ::: "memory");
}

__device__ __forceinline__ void ldmatrix_x4(
    uint32_t& r0, uint32_t& r1, uint32_t& r2, uint32_t& r3, uint32_t addr)
{
    asm volatile("ldmatrix.sync.aligned.m8n8.x4.shared.b16 {%0,%1,%2,%3}, [%4];"
                 : "=r"(r0), "=r"(r1), "=r"(r2), "=r"(r3) : "r"(addr));
}

__device__ __forceinline__ void mma_16816(
    float& c0, float& c1, float& c2, float& c3,
    uint32_t a0, uint32_t a1, uint32_t a2, uint32_t a3,
    uint32_t b0, uint32_t b1)
{
    asm volatile(
        "mma.sync.aligned.m16n8k16.row.col.f32.bf16.bf16.f32 "
        "{%0,%1,%2,%3}, {%4,%5,%6,%7}, {%8,%9}, {%0,%1,%2,%3};"
        : "+f"(c0), "+f"(c1), "+f"(c2), "+f"(c3)
        : "r"(a0), "r"(a1), "r"(a2), "r"(a3), "r"(b0), "r"(b1));
}

// ---------------------------------------------------------------------------
// Convert kernels: fp32 -> bf16 hi/lo split
// ---------------------------------------------------------------------------
__device__ __forceinline__ uint32_t pack_bf16x2(__nv_bfloat16 a, __nv_bfloat16 b) {
    return (uint32_t)__bfloat16_as_ushort(a) | ((uint32_t)__bfloat16_as_ushort(b) << 16);
}

__global__ __launch_bounds__(256) void convert_x(const float* __restrict__ x)
{
    size_t i = (size_t)blockIdx.x * 256 + threadIdx.x;
    float4 v = ((const float4*)x)[i];
    __nv_bfloat16 h0 = __float2bfloat16_rn(v.x);
    __nv_bfloat16 h1 = __float2bfloat16_rn(v.y);
    __nv_bfloat16 h2 = __float2bfloat16_rn(v.z);
    __nv_bfloat16 h3 = __float2bfloat16_rn(v.w);
    __nv_bfloat16 l0 = __float2bfloat16_rn(v.x - __bfloat162float(h0));
    __nv_bfloat16 l1 = __float2bfloat16_rn(v.y - __bfloat162float(h1));
    __nv_bfloat16 l2 = __float2bfloat16_rn(v.z - __bfloat162float(h2));
    __nv_bfloat16 l3 = __float2bfloat16_rn(v.w - __bfloat162float(h3));
    ((uint2*)g_xh)[i] = make_uint2(pack_bf16x2(h0, h1), pack_bf16x2(h2, h3));
    ((uint2*)g_xl)[i] = make_uint2(pack_bf16x2(l0, l1), pack_bf16x2(l2, l3));
}

__global__ __launch_bounds__(256) void convert_w(
    const float* __restrict__ Wq, const float* __restrict__ Wk, const float* __restrict__ Wv)
{
    const float* W = (blockIdx.y == 0) ? Wq : (blockIdx.y == 1) ? Wk : Wv;
    size_t base = (size_t)blockIdx.y * (DD * DD / 4);
    size_t i = (size_t)blockIdx.x * 256 + threadIdx.x;
    float4 v = ((const float4*)W)[i];
    __nv_bfloat16 h0 = __float2bfloat16_rn(v.x);
    __nv_bfloat16 h1 = __float2bfloat16_rn(v.y);
    __nv_bfloat16 h2 = __float2bfloat16_rn(v.z);
    __nv_bfloat16 h3 = __float2bfloat16_rn(v.w);
    __nv_bfloat16 l0 = __float2bfloat16_rn(v.x - __bfloat162float(h0));
    __nv_bfloat16 l1 = __float2bfloat16_rn(v.y - __bfloat162float(h1));
    __nv_bfloat16 l2 = __float2bfloat16_rn(v.z - __bfloat162float(h2));
    __nv_bfloat16 l3 = __float2bfloat16_rn(v.w - __bfloat162float(h3));
    ((uint2*)g_wh)[base + i] = make_uint2(pack_bf16x2(h0, h1), pack_bf16x2(h2, h3));
    ((uint2*)g_wl)[base + i] = make_uint2(pack_bf16x2(l0, l1), pack_bf16x2(l2, l3));
}

// ---------------------------------------------------------------------------
// QKV projection GEMM via mma.sync bf16 (split-fp32).
// C[r,e] = sum over K'=1536: A' = [xh|xh|xl], B' = [wh|wl|wh].
// CTA: 128x256 tile, 8 warps (2m x 4n), warp tile 64x64.
// K'=1536 streamed in 24 chunks of 64 bf16, 3-stage cp.async pipeline,
// single __syncthreads per chunk (prefetch issued after the barrier into the
// stage drained by it).
// grid = (2 n-tiles, 256 m-tiles, 3 projections), 256 threads.
// ---------------------------------------------------------------------------
#define STAGE_A    16384u            // 128 rows x 128 B
#define STAGE_BYTES 49152u           // A 16KB + B 32KB (256 rows x 128 B)
#define SMEM_DYN (3 * STAGE_BYTES + 1024)

__global__ __launch_bounds__(256, 1) void qkv_mma(
    const float* __restrict__ bq, const float* __restrict__ bk, const float* __restrict__ bv)
{
    extern __shared__ __align__(16) char dsm[];
    const uint32_t raw  = smem_to_u32(dsm);
    const uint32_t base = (raw + 1023u) & ~1023u;

    const int tid  = threadIdx.x;
    const int wid  = tid >> 5;
    const int lane = tid & 31;
    const int wm   = wid & 1;          // m block of 64
    const int wn   = wid >> 1;         // 0..3, n block of 64
    const int gid  = lane >> 2;
    const int tig  = lane & 3;

    const int z    = blockIdx.z;
    const int row0 = blockIdx.y * 128;
    const int col0 = blockIdx.x * 256;

    const __nv_bfloat16* whz = g_wh + (size_t)z * (DD * DD);
    const __nv_bfloat16* wlz = g_wl + (size_t)z * (DD * DD);

    // Swizzled ldmatrix base addresses (kk=0); kk advances via ^(kk<<5)
    uint32_t aAddr[4];
#pragma unroll
    for (int mf = 0; mf < 4; mf++) {
        int r = wm * 64 + mf * 16 + (lane & 15);
        uint32_t t = (uint32_t)((lane >> 4) * 16);
        aAddr[mf] = base + r * 128 + (t ^ ((uint32_t)(r & 7) * 16));
    }
    uint32_t bAddr[4];
#pragma unroll
    for (int bh = 0; bh < 4; bh++) {
        int n = wn * 64 + bh * 16 + (lane & 7) + ((lane >> 4) & 1) * 8;
        uint32_t t = (uint32_t)(((lane >> 3) & 1) * 16);
        bAddr[bh] = base + STAGE_A + n * 128 + (t ^ ((uint32_t)(n & 7) * 16));
    }

    float c[4][8][4];
#pragma unroll
    for (int mf = 0; mf < 4; mf++)
#pragma unroll
        for (int nf = 0; nf < 8; nf++)
#pragma unroll
            for (int q = 0; q < 4; q++) c[mf][nf][q] = 0.0f;

    auto issue_chunk = [&](int ci, int s) {
        const __nv_bfloat16* Asrc = (ci < 16) ? g_xh : g_xl;
        const __nv_bfloat16* Bsrc = (ci >= 8 && ci < 16) ? wlz : whz;
        const int koff = (ci & 7) * 64;
        const uint32_t stage = base + (uint32_t)s * STAGE_BYTES;
        // A: 128 rows x 8 x 16B = 1024 uint4, 4 per thread
#pragma unroll
        for (int j = 0; j < 4; j++) {
            int idx = tid + j * 256;
            int r = idx >> 3, o = idx & 7;
            uint32_t bo = (uint32_t)(r * 128 + o * 16);
            cp_async16(stage + SMEM_SWIZZLE_128B(bo),
                       Asrc + (size_t)(row0 + r) * DD + koff + o * 8);
        }
        // B: 256 rows x 8 x 16B = 2048 uint4, 8 per thread
#pragma unroll
        for (int j = 0; j < 8; j++) {
            int idx = tid + j * 256;
            int n = idx >> 3, o = idx & 7;
            uint32_t bo = (uint32_t)(n * 128 + o * 16);
            cp_async16(stage + STAGE_A + SMEM_SWIZZLE_128B(bo),
                       Bsrc + (size_t)(col0 + n) * DD + koff + o * 8);
        }
        cp_commit();
    };

    issue_chunk(0, 0);
    issue_chunk(1, 1);

    for (int ck = 0; ck < 24; ck++) {
        if (ck < 23) cp_wait1(); else cp_wait0();
        __syncthreads();
        // Prefetch into stage (ck+2)%3 == (ck-1)%3 — drained by the barrier above.
        if (ck + 2 < 24) issue_chunk(ck + 2, (ck + 2) % 3);

        const uint32_t soff = (uint32_t)(ck % 3) * STAGE_BYTES;
#pragma unroll
        for (int kk = 0; kk < 4; kk++) {
            const uint32_t kx = (uint32_t)(kk << 5);
            uint32_t a[4][4];
#pragma unroll
            for (int mf = 0; mf < 4; mf++)
                ldmatrix_x4(a[mf][0], a[mf][1], a[mf][2], a[mf][3],
                            (aAddr[mf] + soff) ^ kx);
            uint32_t b[8][2];
#pragma unroll
            for (int bh = 0; bh < 4; bh++) {
                uint32_t r0, r1, r2, r3;
                ldmatrix_x4(r0, r1, r2, r3, (bAddr[bh] + soff) ^ kx);
                b[bh * 2 + 0][0] = r0; b[bh * 2 + 0][1] = r1;
                b[bh * 2 + 1][0] = r2; b[bh * 2 + 1][1] = r3;
            }
#pragma unroll
            for (int mf = 0; mf < 4; mf++)
#pragma unroll
                for (int nf = 0; nf < 8; nf++)
                    mma_16816(c[mf][nf][0], c[mf][nf][1], c[mf][nf][2], c[mf][nf][3],
                              a[mf][0], a[mf][1], a[mf][2], a[mf][3],
                              b[nf][0], b[nf][1]);
        }
    }

    float* out = (z == 0) ? g_Q : (z == 1) ? g_K : g_V;
    const float* bias = (z == 0) ? bq : (z == 1) ? bk : bv;

#pragma unroll
    for (int nf = 0; nf < 8; nf++) {
        const int col = col0 + wn * 64 + nf * 8 + tig * 2;
        float2 bb = *(const float2*)(bias + col);
#pragma unroll
        for (int mf = 0; mf < 4; mf++) {
            const int r0 = row0 + wm * 64 + mf * 16 + gid;
            float2 v0 = make_float2(c[mf][nf][0] + bb.x, c[mf][nf][1] + bb.y);
            float2 v1 = make_float2(c[mf][nf][2] + bb.x, c[mf][nf][3] + bb.y);
            *(float2*)(out + (size_t)r0 * DD + col)       = v0;
            *(float2*)(out + (size_t)(r0 + 8) * DD + col) = v1;
        }
    }
}

// ---------------------------------------------------------------------------
// Kernel 2: attention scores + softmax (smem-staged, register-tiled 4x4).
// ---------------------------------------------------------------------------
__global__ __launch_bounds__(256) void score_softmax()
{
    __shared__ float sQ[4096];        // [4b][8m][128d]
    __shared__ float sK[4096];
    __shared__ float part[64 * 65];   // [h=b*16+slice][pair], padded
    __shared__ float sc[64];
    __shared__ float es[64];

    const int tn  = blockIdx.x;
    const int tid = threadIdx.x;
    const int b    = tid >> 6;
    const int r    = tid & 63;
    const int tile = r >> 4;
    const int slc  = r & 15;
    const int mt   = tile >> 1;
    const int kt   = tile & 1;

    float acc[4][4];
#pragma unroll
    for (int i = 0; i < 4; i++)
#pragma unroll
        for (int j = 0; j < 4; j++) acc[i][j] = 0.0f;

    const float4* Q4 = (const float4*)g_Q;
    const float4* K4 = (const float4*)g_K;

    for (int ch = 0; ch < 4; ch++) {
        __syncthreads();
#pragma unroll
        for (int j = 0; j < 4; j++) {
            int idx = tid + j * 256;
            int lb = idx >> 8, lrr = (idx >> 5) & 7, o = idx & 31;
            size_t grow = (size_t)lb * TNM + (size_t)tn * MM + lrr;
            ((float4*)sQ)[(lb * 8 + lrr) * 32 + o] = Q4[grow * (DD / 4) + ch * 32 + o];
            ((float4*)sK)[(lb * 8 + lrr) * 32 + o] = K4[grow * (DD / 4) + ch * 32 + o];
        }
        __syncthreads();

#pragma unroll
        for (int j = 0; j < 2; j++) {
            const int d4 = j * 16 + slc;
            float4 qf[4], kf[4];
#pragma unroll
            for (int i = 0; i < 4; i++)
                qf[i] = ((const float4*)sQ)[(b * 8 + mt * 4 + i) * 32 + d4];
#pragma unroll
            for (int i = 0; i < 4; i++)
                kf[i] = ((const float4*)sK)[(b * 8 + kt * 4 + i) * 32 + d4];
#pragma unroll
            for (int i = 0; i < 4; i++)
#pragma unroll
                for (int kx = 0; kx < 4; kx++) {
                    acc[i][kx] = fmaf(qf[i].x, kf[kx].x, acc[i][kx]);
                    acc[i][kx] = fmaf(qf[i].y, kf[kx].y, acc[i][kx]);
                    acc[i][kx] = fmaf(qf[i].z, kf[kx].z, acc[i][kx]);
                    acc[i][kx] = fmaf(qf[i].w, kf[kx].w, acc[i][kx]);
                }
        }
    }

    const int h = b * 16 + slc;
#pragma unroll
    for (int i = 0; i < 4; i++)
#pragma unroll
        for (int kx = 0; kx < 4; kx++) {
            int pair = (mt * 4 + i) * 8 + (kt * 4 + kx);
            part[h * 65 + pair] = acc[i][kx];
        }
    __syncthreads();

    if (tid < 64) {
        float s = 0.0f;
#pragma unroll
        for (int i = 0; i < 64; i++) s += part[i * 65 + tid];
        sc[tid] = s * 0.04419417382415922f;   // 1/sqrt(512)
    }
    __syncthreads();

    if (tid < 64) {
        const int m = tid >> 3;
        float mx = sc[m * 8];
#pragma unroll
        for (int j = 1; j < 8; j++) mx = fmaxf(mx, sc[m * 8 + j]);
        es[tid] = expf(sc[tid] - mx);
    }
    __syncthreads();

    if (tid < 64) {
        const int m = tid >> 3;
        float sum = 0.0f;
#pragma unroll
        for (int j = 0; j < 8; j++) sum += es[m * 8 + j];
        g_W[tn * 64 + tid] = es[tid] / sum;
    }
}

// ---------------------------------------------------------------------------
// Kernel 3: weighted V sum
// ---------------------------------------------------------------------------
__global__ __launch_bounds__(256) void out_kernel(float* __restrict__ out)
{
    const int btn = blockIdx.x;
    const int tid = threadIdx.x;
    const int d4  = tid & 127;
    const int mh  = tid >> 7;
    const int tn  = btn % (TT * NN);

    __shared__ float w[64];
    if (tid < 64) w[tid] = g_W[tn * 64 + tid];
    __syncthreads();

    const float4* V4 = (const float4*)(g_V + (size_t)btn * MM * DD);
    float4* O4 = (float4*)(out + (size_t)btn * MM * DD);

    float4 acc[4];
#pragma unroll
    for (int i = 0; i < 4; i++) acc[i] = make_float4(0.f, 0.f, 0.f, 0.f);

#pragma unroll
    for (int k = 0; k < 8; k++) {
        float4 v = V4[k * (DD / 4) + d4];
#pragma unroll
        for (int i = 0; i < 4; i++) {
            float wm = w[(mh * 4 + i) * 8 + k];
            acc[i].x = fmaf(wm, v.x, acc[i].x);
            acc[i].y = fmaf(wm, v.y, acc[i].y);
            acc[i].z = fmaf(wm, v.z, acc[i].z);
            acc[i].w = fmaf(wm, v.w, acc[i].w);
        }
    }

#pragma unroll
    for (int i = 0; i < 4; i++) {
        O4[(mh * 4 + i) * (DD / 4) + d4] = acc[i];
    }
}

// ---------------------------------------------------------------------------
extern "C" void kernel_launch(void* const* d_in, const int* in_sizes, int n_in,
                              void* d_out, int out_size)
{
    const float* x  = (const float*)d_in[0];
    const float* Wq = (const float*)d_in[1];
    const float* bq = (const float*)d_in[2];
    const float* Wk = (const float*)d_in[3];
    const float* bk = (const float*)d_in[4];
    const float* Wv = (const float*)d_in[5];
    const float* bv = (const float*)d_in[6];

    cudaFuncSetAttribute(qkv_mma, cudaFuncAttributeMaxDynamicSharedMemorySize, SMEM_DYN);

    convert_x<<<(ROWS * DD / 4) / 256, 256>>>(x);
    convert_w<<<dim3((DD * DD / 4) / 256, 3), 256>>>(Wq, Wk, Wv);
    qkv_mma<<<dim3(2, ROWS / 128, 3), 256, SMEM_DYN>>>(bq, bk, bv);
    score_softmax<<<TT * NN, 256>>>();
    out_kernel<<<BB * TT * NN, 256>>>((float*)d_out);
}

// round 11
// speedup vs baseline: 3.8834x; 1.1473x over previous
#include <cuda_runtime.h>
#include <cuda_bf16.h>
#include <cstdint>

// Problem dims
#define BB 4
#define TT 64
#define NN 16
#define MM 8
#define DD 512
#define ROWS (BB * TT * NN * MM)   // 32768 flattened (b,t,n,m) rows
#define TNM  (TT * NN * MM)

// ---------------------------------------------------------------------------
// Scratch (__device__ globals; allocation-free rule)
// ---------------------------------------------------------------------------
__device__ float g_Z[(size_t)ROWS * DD];     // Z = x * (Wq^T Wk)
__device__ float g_V[(size_t)ROWS * DD];
__device__ float g_W[TT * NN * MM * MM];
__device__ float g_u[DD];                    // Wq^T bk
__device__ float g_v[DD];                    // Wk^T bq
__device__ float g_c;                        // bq . bk

__device__ __align__(16) __nv_bfloat16 g_xh[(size_t)ROWS * DD];
__device__ __align__(16) __nv_bfloat16 g_xl[(size_t)ROWS * DD];
__device__ __align__(16) __nv_bfloat16 g_wh[2 * DD * DD];   // z=0: Gt, z=1: Wv
__device__ __align__(16) __nv_bfloat16 g_wl[2 * DD * DD];

// ---------------------------------------------------------------------------
// Helpers
// ---------------------------------------------------------------------------
__device__ __forceinline__ uint32_t smem_to_u32(const void* smem_ptr) {
    uint32_t addr;
    asm("{ .reg .u64 tmp; cvta.to.shared.u64 tmp, %1; cvt.u32.u64 %0, tmp; }"
        : "=r"(addr) : "l"(smem_ptr));
    return addr;
}

#define SMEM_SWIZZLE_128B(byte_offset) \
    ((byte_offset) ^ (((byte_offset) >> 3) & 0x70))

__device__ __forceinline__ void cp_async16(uint32_t dst, const void* src) {
    asm volatile("cp.async.cg.shared.global [%0], [%1], 16;"
                 :: "r"(dst), "l"(src) : "memory");
}
__device__ __forceinline__ void cp_commit() {
    asm volatile("cp.async.commit_group;" ::: "memory");
}
__device__ __forceinline__ void cp_wait2() {
    asm volatile("cp.async.wait_group 2;" ::: "memory");
}
__device__ __forceinline__ void cp_wait1() {
    asm volatile("cp.async.wait_group 1;" ::: "memory");
}
__device__ __forceinline__ void cp_wait0() {
    asm volatile("cp.async.wait_group 0;" ::: "memory");
}

__device__ __forceinline__ void ldmatrix_x4(
    uint32_t& r0, uint32_t& r1, uint32_t& r2, uint32_t& r3, uint32_t addr)
{
    asm volatile("ldmatrix.sync.aligned.m8n8.x4.shared.b16 {%0,%1,%2,%3}, [%4];"
                 : "=r"(r0), "=r"(r1), "=r"(r2), "=r"(r3) : "r"(addr));
}

__device__ __forceinline__ void mma_16816(
    float& c0, float& c1, float& c2, float& c3,
    uint32_t a0, uint32_t a1, uint32_t a2, uint32_t a3,
    uint32_t b0, uint32_t b1)
{
    asm volatile(
        "mma.sync.aligned.m16n8k16.row.col.f32.bf16.bf16.f32 "
        "{%0,%1,%2,%3}, {%4,%5,%6,%7}, {%8,%9}, {%0,%1,%2,%3};"
        : "+f"(c0), "+f"(c1), "+f"(c2), "+f"(c3)
        : "r"(a0), "r"(a1), "r"(a2), "r"(a3), "r"(b0), "r"(b1));
}

__device__ __forceinline__ uint32_t pack_bf16x2(__nv_bfloat16 a, __nv_bfloat16 b) {
    return (uint32_t)__bfloat16_as_ushort(a) | ((uint32_t)__bfloat16_as_ushort(b) << 16);
}

// ---------------------------------------------------------------------------
// Precompute Gt[j,i] = sum_e Wk[e,j] * Wq[e,i]  (= (Wq^T Wk)^T, k-major for MMA B)
// Written directly as bf16 hi/lo into slot 0 of g_wh/g_wl.
// Grid (8,8), 256 threads, 64x64 tile, k-slab 16.
// ---------------------------------------------------------------------------
__global__ __launch_bounds__(256) void gemm_G(
    const float* __restrict__ Wq, const float* __restrict__ Wk)
{
    __shared__ float Ak[16][68];   // [e][j]
    __shared__ float Bk[16][68];   // [e][i]

    const int tid = threadIdx.x;
    const int j0 = blockIdx.y * 64;
    const int i0 = blockIdx.x * 64;
    const int le = tid >> 4;           // 0..15
    const int lc = (tid & 15) * 4;
    const int ty = tid >> 4;
    const int tx = tid & 15;

    float acc[4][4];
#pragma unroll
    for (int a = 0; a < 4; a++)
#pragma unroll
        for (int b = 0; b < 4; b++) acc[a][b] = 0.0f;

    for (int e0 = 0; e0 < DD; e0 += 16) {
        __syncthreads();
        *(float4*)&Ak[le][lc] = *(const float4*)(Wk + (size_t)(e0 + le) * DD + j0 + lc);
        *(float4*)&Bk[le][lc] = *(const float4*)(Wq + (size_t)(e0 + le) * DD + i0 + lc);
        __syncthreads();
#pragma unroll
        for (int e = 0; e < 16; e++) {
            float4 a4 = *(const float4*)&Ak[e][ty * 4];
            float4 b4 = *(const float4*)&Bk[e][tx * 4];
            float ar[4] = {a4.x, a4.y, a4.z, a4.w};
            float br[4] = {b4.x, b4.y, b4.z, b4.w};
#pragma unroll
            for (int a = 0; a < 4; a++)
#pragma unroll
                for (int b = 0; b < 4; b++)
                    acc[a][b] = fmaf(ar[a], br[b], acc[a][b]);
        }
    }

#pragma unroll
    for (int a = 0; a < 4; a++) {
        const int j = j0 + ty * 4 + a;
        const size_t off = (size_t)j * DD + i0 + tx * 4;
        __nv_bfloat16 h[4], l[4];
#pragma unroll
        for (int b = 0; b < 4; b++) {
            h[b] = __float2bfloat16_rn(acc[a][b]);
            l[b] = __float2bfloat16_rn(acc[a][b] - __bfloat162float(h[b]));
        }
        *(uint2*)(g_wh + off) = make_uint2(pack_bf16x2(h[0], h[1]), pack_bf16x2(h[2], h[3]));
        *(uint2*)(g_wl + off) = make_uint2(pack_bf16x2(l[0], l[1]), pack_bf16x2(l[2], l[3]));
    }
}

// ---------------------------------------------------------------------------
// u[i] = sum_e Wq[e,i]*bk[e];  v[i] = sum_e Wk[e,i]*bq[e];  c = bq.bk
// Grid 4 blocks x 128 threads (i = blk*128+tid).
// ---------------------------------------------------------------------------
__global__ __launch_bounds__(128) void bias_uvc(
    const float* __restrict__ Wq, const float* __restrict__ bq,
    const float* __restrict__ Wk, const float* __restrict__ bk)
{
    const int i = blockIdx.x * 128 + threadIdx.x;
    float u = 0.0f, v = 0.0f;
#pragma unroll 4
    for (int e = 0; e < DD; e++) {
        u = fmaf(Wq[(size_t)e * DD + i], bk[e], u);
        v = fmaf(Wk[(size_t)e * DD + i], bq[e], v);
    }
    g_u[i] = u;
    g_v[i] = v;

    if (blockIdx.x == 0) {
        __shared__ float red[128];
        float s = 0.0f;
#pragma unroll
        for (int j = 0; j < 4; j++) s = fmaf(bq[threadIdx.x + j * 128], bk[threadIdx.x + j * 128], s);
        red[threadIdx.x] = s;
        __syncthreads();
        for (int st = 64; st > 0; st >>= 1) {
            if (threadIdx.x < st) red[threadIdx.x] += red[threadIdx.x + st];
            __syncthreads();
        }
        if (threadIdx.x == 0) g_c = red[0];
    }
}

// ---------------------------------------------------------------------------
// Convert kernels: fp32 -> bf16 hi/lo split
// ---------------------------------------------------------------------------
__global__ __launch_bounds__(256) void convert_x(const float* __restrict__ x)
{
    size_t i = (size_t)blockIdx.x * 256 + threadIdx.x;
    float4 v = ((const float4*)x)[i];
    __nv_bfloat16 h0 = __float2bfloat16_rn(v.x);
    __nv_bfloat16 h1 = __float2bfloat16_rn(v.y);
    __nv_bfloat16 h2 = __float2bfloat16_rn(v.z);
    __nv_bfloat16 h3 = __float2bfloat16_rn(v.w);
    __nv_bfloat16 l0 = __float2bfloat16_rn(v.x - __bfloat162float(h0));
    __nv_bfloat16 l1 = __float2bfloat16_rn(v.y - __bfloat162float(h1));
    __nv_bfloat16 l2 = __float2bfloat16_rn(v.z - __bfloat162float(h2));
    __nv_bfloat16 l3 = __float2bfloat16_rn(v.w - __bfloat162float(h3));
    ((uint2*)g_xh)[i] = make_uint2(pack_bf16x2(h0, h1), pack_bf16x2(h2, h3));
    ((uint2*)g_xl)[i] = make_uint2(pack_bf16x2(l0, l1), pack_bf16x2(l2, l3));
}

// Converts Wv into slot 1 of g_wh/g_wl.
__global__ __launch_bounds__(256) void convert_w(const float* __restrict__ Wv)
{
    size_t base = (size_t)(DD * DD / 4);
    size_t i = (size_t)blockIdx.x * 256 + threadIdx.x;
    float4 v = ((const float4*)Wv)[i];
    __nv_bfloat16 h0 = __float2bfloat16_rn(v.x);
    __nv_bfloat16 h1 = __float2bfloat16_rn(v.y);
    __nv_bfloat16 h2 = __float2bfloat16_rn(v.z);
    __nv_bfloat16 h3 = __float2bfloat16_rn(v.w);
    __nv_bfloat16 l0 = __float2bfloat16_rn(v.x - __bfloat162float(h0));
    __nv_bfloat16 l1 = __float2bfloat16_rn(v.y - __bfloat162float(h1));
    __nv_bfloat16 l2 = __float2bfloat16_rn(v.z - __bfloat162float(h2));
    __nv_bfloat16 l3 = __float2bfloat16_rn(v.w - __bfloat162float(h3));
    ((uint2*)g_wh)[base + i] = make_uint2(pack_bf16x2(h0, h1), pack_bf16x2(h2, h3));
    ((uint2*)g_wl)[base + i] = make_uint2(pack_bf16x2(l0, l1), pack_bf16x2(l2, l3));
}

// ---------------------------------------------------------------------------
// Z/V GEMM via mma.sync bf16 (split-fp32), exact R7 schedule.
// z=0: Z = x*Gt^T (no bias); z=1: V = x*Wv^T + bv.
// CTA 128x128, 4 warps (2m x 2n), warp tile 64x64, 3-stage cp.async.
// grid = (4 n-tiles, 256 m-tiles, 2), 128 threads.
// ---------------------------------------------------------------------------
#define STAGE_BYTES 32768u   // A 16KB + B 16KB
#define SMEM_DYN (3 * STAGE_BYTES + 1024)

__global__ __launch_bounds__(128, 1) void qkv_mma(const float* __restrict__ bv)
{
    extern __shared__ __align__(16) char dsm[];
    const uint32_t raw  = smem_to_u32(dsm);
    const uint32_t base = (raw + 1023u) & ~1023u;

    const int tid  = threadIdx.x;
    const int wid  = tid >> 5;
    const int lane = tid & 31;
    const int wm   = wid & 1;
    const int wn   = wid >> 1;
    const int gid  = lane >> 2;
    const int tig  = lane & 3;

    const int z    = blockIdx.z;       // 0: Z, 1: V
    const int row0 = blockIdx.y * 128;
    const int col0 = blockIdx.x * 128;

    const __nv_bfloat16* whz = g_wh + (size_t)z * (DD * DD);
    const __nv_bfloat16* wlz = g_wl + (size_t)z * (DD * DD);

    uint32_t aAddr[4];
#pragma unroll
    for (int mf = 0; mf < 4; mf++) {
        int r = wm * 64 + mf * 16 + (lane & 15);
        uint32_t t = (uint32_t)((lane >> 4) * 16);
        aAddr[mf] = base + r * 128 + (t ^ ((uint32_t)(r & 7) * 16));
    }
    uint32_t bAddr[4];
#pragma unroll
    for (int bh = 0; bh < 4; bh++) {
        int n = wn * 64 + bh * 16 + (lane & 7) + ((lane >> 4) & 1) * 8;
        uint32_t t = (uint32_t)(((lane >> 3) & 1) * 16);
        bAddr[bh] = base + 16384u + n * 128 + (t ^ ((uint32_t)(n & 7) * 16));
    }

    float c[4][8][4];
#pragma unroll
    for (int mf = 0; mf < 4; mf++)
#pragma unroll
        for (int nf = 0; nf < 8; nf++)
#pragma unroll
            for (int q = 0; q < 4; q++) c[mf][nf][q] = 0.0f;

    auto issue_chunk = [&](int ci, int s) {
        const __nv_bfloat16* Asrc = (ci < 16) ? g_xh : g_xl;
        const __nv_bfloat16* Bsrc = (ci >= 8 && ci < 16) ? wlz : whz;
        const int koff = (ci & 7) * 64;
        const uint32_t stage = base + (uint32_t)s * STAGE_BYTES;
#pragma unroll
        for (int j = 0; j < 8; j++) {
            int idx = tid + j * 128;
            int r = idx >> 3, o = idx & 7;
            uint32_t bo = (uint32_t)(r * 128 + o * 16);
            cp_async16(stage + SMEM_SWIZZLE_128B(bo),
                       Asrc + (size_t)(row0 + r) * DD + koff + o * 8);
        }
#pragma unroll
        for (int j = 0; j < 8; j++) {
            int idx = tid + j * 128;
            int n = idx >> 3, o = idx & 7;
            uint32_t bo = (uint32_t)(n * 128 + o * 16);
            cp_async16(stage + 16384u + SMEM_SWIZZLE_128B(bo),
                       Bsrc + (size_t)(col0 + n) * DD + koff + o * 8);
        }
        cp_commit();
    };

    issue_chunk(0, 0);
    issue_chunk(1, 1);

    for (int ck = 0; ck < 24; ck++) {
        if (ck + 2 < 24) issue_chunk(ck + 2, (ck + 2) % 3);
        if (ck < 22) cp_wait2();
        else if (ck == 22) cp_wait1();
        else cp_wait0();
        __syncthreads();

        const uint32_t soff = (uint32_t)(ck % 3) * STAGE_BYTES;
#pragma unroll
        for (int kk = 0; kk < 4; kk++) {
            const uint32_t kx = (uint32_t)(kk << 5);
            uint32_t a[4][4];
#pragma unroll
            for (int mf = 0; mf < 4; mf++)
                ldmatrix_x4(a[mf][0], a[mf][1], a[mf][2], a[mf][3],
                            (aAddr[mf] + soff) ^ kx);
            uint32_t b[8][2];
#pragma unroll
            for (int bh = 0; bh < 4; bh++) {
                uint32_t r0, r1, r2, r3;
                ldmatrix_x4(r0, r1, r2, r3, (bAddr[bh] + soff) ^ kx);
                b[bh * 2 + 0][0] = r0; b[bh * 2 + 0][1] = r1;
                b[bh * 2 + 1][0] = r2; b[bh * 2 + 1][1] = r3;
            }
#pragma unroll
            for (int mf = 0; mf < 4; mf++)
#pragma unroll
                for (int nf = 0; nf < 8; nf++)
                    mma_16816(c[mf][nf][0], c[mf][nf][1], c[mf][nf][2], c[mf][nf][3],
                              a[mf][0], a[mf][1], a[mf][2], a[mf][3],
                              b[nf][0], b[nf][1]);
        }
        __syncthreads();
    }

    float* out = (z == 0) ? g_Z : g_V;

#pragma unroll
    for (int nf = 0; nf < 8; nf++) {
        const int col = col0 + wn * 64 + nf * 8 + tig * 2;
        float2 bb = (z == 1) ? *(const float2*)(bv + col) : make_float2(0.0f, 0.0f);
#pragma unroll
        for (int mf = 0; mf < 4; mf++) {
            const int r0 = row0 + wm * 64 + mf * 16 + gid;
            float2 v0 = make_float2(c[mf][nf][0] + bb.x, c[mf][nf][1] + bb.y);
            float2 v1 = make_float2(c[mf][nf][2] + bb.x, c[mf][nf][3] + bb.y);
            *(float2*)(out + (size_t)r0 * DD + col)       = v0;
            *(float2*)(out + (size_t)(r0 + 8) * DD + col) = v1;
        }
    }
}

// ---------------------------------------------------------------------------
// Kernel 2: scores + softmax.
// score[m,k] = (Sum_b Sum_d Z[b,m,d]*x[b,k,d] + P[m] + R[k] + 4c) * scale
// where P[m] = Sum_b x[b,m].u,  R[k] = Sum_b x[b,k].v.
// One block per (t,n), 256 threads; Z and x staged per 128-d chunk.
// ---------------------------------------------------------------------------
__global__ __launch_bounds__(256) void score_softmax(const float* __restrict__ x)
{
    __shared__ float sQ[4096];        // Z rows   [4b][8][128]
    __shared__ float sK[4096];        // x rows   [4b][8][128]
    __shared__ float part[64 * 65];
    __shared__ float Pp[4][8][9];
    __shared__ float Rp[4][8][9];
    __shared__ float PP[8], RR[8];
    __shared__ float sc[64];
    __shared__ float es[64];

    const int tn  = blockIdx.x;
    const int tid = threadIdx.x;
    const int b    = tid >> 6;
    const int r    = tid & 63;
    const int tile = r >> 4;
    const int slc  = r & 15;
    const int mt   = tile >> 1;
    const int kt   = tile & 1;

    // P/R accumulation mapping
    const int pb   = tid >> 6;
    const int prow = (tid >> 3) & 7;
    const int ps8  = tid & 7;

    float acc[4][4];
#pragma unroll
    for (int i = 0; i < 4; i++)
#pragma unroll
        for (int j = 0; j < 4; j++) acc[i][j] = 0.0f;
    float pr = 0.0f, rr = 0.0f;

    const float4* Z4 = (const float4*)g_Z;
    const float4* X4 = (const float4*)x;
    const float4* u4 = (const float4*)g_u;
    const float4* v4 = (const float4*)g_v;

    for (int ch = 0; ch < 4; ch++) {
        __syncthreads();
#pragma unroll
        for (int j = 0; j < 4; j++) {
            int idx = tid + j * 256;
            int lb = idx >> 8, lrr = (idx >> 5) & 7, o = idx & 31;
            size_t grow = (size_t)lb * TNM + (size_t)tn * MM + lrr;
            ((float4*)sQ)[(lb * 8 + lrr) * 32 + o] = Z4[grow * (DD / 4) + ch * 32 + o];
            ((float4*)sK)[(lb * 8 + lrr) * 32 + o] = X4[grow * (DD / 4) + ch * 32 + o];
        }
        __syncthreads();

        // main dot 4x4
#pragma unroll
        for (int j = 0; j < 2; j++) {
            const int d4 = j * 16 + slc;
            float4 qf[4], kf[4];
#pragma unroll
            for (int i = 0; i < 4; i++)
                qf[i] = ((const float4*)sQ)[(b * 8 + mt * 4 + i) * 32 + d4];
#pragma unroll
            for (int i = 0; i < 4; i++)
                kf[i] = ((const float4*)sK)[(b * 8 + kt * 4 + i) * 32 + d4];
#pragma unroll
            for (int i = 0; i < 4; i++)
#pragma unroll
                for (int kx = 0; kx < 4; kx++) {
                    acc[i][kx] = fmaf(qf[i].x, kf[kx].x, acc[i][kx]);
                    acc[i][kx] = fmaf(qf[i].y, kf[kx].y, acc[i][kx]);
                    acc[i][kx] = fmaf(qf[i].z, kf[kx].z, acc[i][kx]);
                    acc[i][kx] = fmaf(qf[i].w, kf[kx].w, acc[i][kx]);
                }
        }

        // P/R partials over this thread's 16-d slice
#pragma unroll
        for (int w = 0; w < 4; w++) {
            float4 xv = ((const float4*)sK)[(pb * 8 + prow) * 32 + ps8 * 4 + w];
            float4 uu = u4[ch * 32 + ps8 * 4 + w];
            float4 vv = v4[ch * 32 + ps8 * 4 + w];
            pr = fmaf(xv.x, uu.x, pr); pr = fmaf(xv.y, uu.y, pr);
            pr = fmaf(xv.z, uu.z, pr); pr = fmaf(xv.w, uu.w, pr);
            rr = fmaf(xv.x, vv.x, rr); rr = fmaf(xv.y, vv.y, rr);
            rr = fmaf(xv.z, vv.z, rr); rr = fmaf(xv.w, vv.w, rr);
        }
    }

    const int h = b * 16 + slc;
#pragma unroll
    for (int i = 0; i < 4; i++)
#pragma unroll
        for (int kx = 0; kx < 4; kx++) {
            int pair = (mt * 4 + i) * 8 + (kt * 4 + kx);
            part[h * 65 + pair] = acc[i][kx];
        }
    Pp[pb][prow][ps8] = pr;
    Rp[pb][prow][ps8] = rr;
    __syncthreads();

    if (tid < 8) {
        float s = 0.0f;
#pragma unroll
        for (int bb = 0; bb < 4; bb++)
#pragma unroll
            for (int ss = 0; ss < 8; ss++) s += Pp[bb][tid][ss];
        PP[tid] = s;
    } else if (tid < 16) {
        const int m = tid - 8;
        float s = 0.0f;
#pragma unroll
        for (int bb = 0; bb < 4; bb++)
#pragma unroll
            for (int ss = 0; ss < 8; ss++) s += Rp[bb][m][ss];
        RR[m] = s;
    }
    __syncthreads();

    if (tid < 64) {
        float s = 0.0f;
#pragma unroll
        for (int i = 0; i < 64; i++) s += part[i * 65 + tid];
        const int m = tid >> 3, k = tid & 7;
        sc[tid] = (s + PP[m] + RR[k] + 4.0f * g_c) * 0.04419417382415922f;
    }
    __syncthreads();

    if (tid < 64) {
        const int m = tid >> 3;
        float mx = sc[m * 8];
#pragma unroll
        for (int j = 1; j < 8; j++) mx = fmaxf(mx, sc[m * 8 + j]);
        es[tid] = expf(sc[tid] - mx);
    }
    __syncthreads();

    if (tid < 64) {
        const int m = tid >> 3;
        float sum = 0.0f;
#pragma unroll
        for (int j = 0; j < 8; j++) sum += es[m * 8 + j];
        g_W[tn * 64 + tid] = es[tid] / sum;
    }
}

// ---------------------------------------------------------------------------
// Kernel 3: weighted V sum
// ---------------------------------------------------------------------------
__global__ __launch_bounds__(256) void out_kernel(float* __restrict__ out)
{
    const int btn = blockIdx.x;
    const int tid = threadIdx.x;
    const int d4  = tid & 127;
    const int mh  = tid >> 7;
    const int tn  = btn % (TT * NN);

    __shared__ float w[64];
    if (tid < 64) w[tid] = g_W[tn * 64 + tid];
    __syncthreads();

    const float4* V4 = (const float4*)(g_V + (size_t)btn * MM * DD);
    float4* O4 = (float4*)(out + (size_t)btn * MM * DD);

    float4 acc[4];
#pragma unroll
    for (int i = 0; i < 4; i++) acc[i] = make_float4(0.f, 0.f, 0.f, 0.f);

#pragma unroll
    for (int k = 0; k < 8; k++) {
        float4 v = V4[k * (DD / 4) + d4];
#pragma unroll
        for (int i = 0; i < 4; i++) {
            float wm = w[(mh * 4 + i) * 8 + k];
            acc[i].x = fmaf(wm, v.x, acc[i].x);
            acc[i].y = fmaf(wm, v.y, acc[i].y);
            acc[i].z = fmaf(wm, v.z, acc[i].z);
            acc[i].w = fmaf(wm, v.w, acc[i].w);
        }
    }

#pragma unroll
    for (int i = 0; i < 4; i++) {
        O4[(mh * 4 + i) * (DD / 4) + d4] = acc[i];
    }
}

// ---------------------------------------------------------------------------
extern "C" void kernel_launch(void* const* d_in, const int* in_sizes, int n_in,
                              void* d_out, int out_size)
{
    const float* x  = (const float*)d_in[0];
    const float* Wq = (const float*)d_in[1];
    const float* bq = (const float*)d_in[2];
    const float* Wk = (const float*)d_in[3];
    const float* bk = (const float*)d_in[4];
    const float* Wv = (const float*)d_in[5];
    const float* bv = (const float*)d_in[6];

    cudaFuncSetAttribute(qkv_mma, cudaFuncAttributeMaxDynamicSharedMemorySize, SMEM_DYN);

    convert_x<<<(ROWS * DD / 4) / 256, 256>>>(x);
    gemm_G<<<dim3(8, 8), 256>>>(Wq, Wk);
    bias_uvc<<<4, 128>>>(Wq, bq, Wk, bk);
    convert_w<<<(DD * DD / 4) / 256, 256>>>(Wv);
    qkv_mma<<<dim3(4, ROWS / 128, 2), 128, SMEM_DYN>>>(bv);
    score_softmax<<<TT * NN, 256>>>(x);
    out_kernel<<<BB * TT * NN, 256>>>((float*)d_out);
}

// round 12
// speedup vs baseline: 4.3302x; 1.1151x over previous
#include <cuda_runtime.h>
#include <cuda_bf16.h>
#include <cstdint>

// Problem dims
#define BB 4
#define TT 64
#define NN 16
#define MM 8
#define DD 512
#define ROWS (BB * TT * NN * MM)   // 32768 flattened (b,t,n,m) rows
#define TNM  (TT * NN * MM)

// ---------------------------------------------------------------------------
// Scratch (__device__ globals; allocation-free rule)
// ---------------------------------------------------------------------------
__device__ float g_Z[(size_t)ROWS * DD];     // Z = x * (Wq^T Wk)
__device__ float g_V[(size_t)ROWS * DD];
__device__ float g_W[TT * NN * MM * MM];
__device__ float g_u[DD];                    // Wq^T bk
__device__ float g_v[DD];                    // Wk^T bq
__device__ float g_c;                        // bq . bk

__device__ __align__(16) __nv_bfloat16 g_xh[(size_t)ROWS * DD];
__device__ __align__(16) __nv_bfloat16 g_xl[(size_t)ROWS * DD];
__device__ __align__(16) __nv_bfloat16 g_wh[2 * DD * DD];   // z=0: Gt, z=1: Wv
__device__ __align__(16) __nv_bfloat16 g_wl[2 * DD * DD];

// ---------------------------------------------------------------------------
// Helpers
// ---------------------------------------------------------------------------
__device__ __forceinline__ uint32_t smem_to_u32(const void* smem_ptr) {
    uint32_t addr;
    asm("{ .reg .u64 tmp; cvta.to.shared.u64 tmp, %1; cvt.u32.u64 %0, tmp; }"
        : "=r"(addr) : "l"(smem_ptr));
    return addr;
}

#define SMEM_SWIZZLE_128B(byte_offset) \
    ((byte_offset) ^ (((byte_offset) >> 3) & 0x70))

__device__ __forceinline__ void cp_async16(uint32_t dst, const void* src) {
    asm volatile("cp.async.cg.shared.global [%0], [%1], 16;"
                 :: "r"(dst), "l"(src) : "memory");
}
__device__ __forceinline__ void cp_commit() {
    asm volatile("cp.async.commit_group;" ::: "memory");
}
__device__ __forceinline__ void cp_wait2() {
    asm volatile("cp.async.wait_group 2;" ::: "memory");
}
__device__ __forceinline__ void cp_wait1() {
    asm volatile("cp.async.wait_group 1;" ::: "memory");
}
__device__ __forceinline__ void cp_wait0() {
    asm volatile("cp.async.wait_group 0;" ::: "memory");
}

__device__ __forceinline__ void ldmatrix_x4(
    uint32_t& r0, uint32_t& r1, uint32_t& r2, uint32_t& r3, uint32_t addr)
{
    asm volatile("ldmatrix.sync.aligned.m8n8.x4.shared.b16 {%0,%1,%2,%3}, [%4];"
                 : "=r"(r0), "=r"(r1), "=r"(r2), "=r"(r3) : "r"(addr));
}

__device__ __forceinline__ void mma_16816(
    float& c0, float& c1, float& c2, float& c3,
    uint32_t a0, uint32_t a1, uint32_t a2, uint32_t a3,
    uint32_t b0, uint32_t b1)
{
    asm volatile(
        "mma.sync.aligned.m16n8k16.row.col.f32.bf16.bf16.f32 "
        "{%0,%1,%2,%3}, {%4,%5,%6,%7}, {%8,%9}, {%0,%1,%2,%3};"
        : "+f"(c0), "+f"(c1), "+f"(c2), "+f"(c3)
        : "r"(a0), "r"(a1), "r"(a2), "r"(a3), "r"(b0), "r"(b1));
}

__device__ __forceinline__ uint32_t pack_bf16x2(__nv_bfloat16 a, __nv_bfloat16 b) {
    return (uint32_t)__bfloat16_as_ushort(a) | ((uint32_t)__bfloat16_as_ushort(b) << 16);
}

// ---------------------------------------------------------------------------
// Precompute Gt[j,i] = sum_e Wk[e,j] * Wq[e,i]  (= (Wq^T Wk)^T, k-major for MMA B)
// Written as bf16 hi/lo into slot 0 of g_wh/g_wl.
// v2: 32x32 tiles, grid (16,16)=256 blocks (full chip), 2x2 microtile.
// ---------------------------------------------------------------------------
__global__ __launch_bounds__(256) void gemm_G(
    const float* __restrict__ Wq, const float* __restrict__ Wk)
{
    __shared__ float Ak[16][36];   // [e][j], padded
    __shared__ float Bk[16][36];   // [e][i]

    const int tid = threadIdx.x;
    const int j0 = blockIdx.y * 32;
    const int i0 = blockIdx.x * 32;
    const int le = tid >> 4;           // 0..15
    const int lc = (tid & 15) * 2;
    const int ty = tid >> 4;           // 0..15 (j pair)
    const int tx = tid & 15;           // 0..15 (i pair)

    float acc[2][2] = {{0.0f, 0.0f}, {0.0f, 0.0f}};

    for (int e0 = 0; e0 < DD; e0 += 16) {
        __syncthreads();
        *(float2*)&Ak[le][lc] = *(const float2*)(Wk + (size_t)(e0 + le) * DD + j0 + lc);
        *(float2*)&Bk[le][lc] = *(const float2*)(Wq + (size_t)(e0 + le) * DD + i0 + lc);
        __syncthreads();
#pragma unroll
        for (int e = 0; e < 16; e++) {
            float a0 = Ak[e][ty * 2], a1 = Ak[e][ty * 2 + 1];
            float b0 = Bk[e][tx * 2], b1 = Bk[e][tx * 2 + 1];
            acc[0][0] = fmaf(a0, b0, acc[0][0]);
            acc[0][1] = fmaf(a0, b1, acc[0][1]);
            acc[1][0] = fmaf(a1, b0, acc[1][0]);
            acc[1][1] = fmaf(a1, b1, acc[1][1]);
        }
    }

#pragma unroll
    for (int a = 0; a < 2; a++) {
        const int j = j0 + ty * 2 + a;
        const size_t off = (size_t)j * DD + i0 + tx * 2;
        __nv_bfloat16 h0 = __float2bfloat16_rn(acc[a][0]);
        __nv_bfloat16 h1 = __float2bfloat16_rn(acc[a][1]);
        __nv_bfloat16 l0 = __float2bfloat16_rn(acc[a][0] - __bfloat162float(h0));
        __nv_bfloat16 l1 = __float2bfloat16_rn(acc[a][1] - __bfloat162float(h1));
        *(uint32_t*)(g_wh + off) = pack_bf16x2(h0, h1);
        *(uint32_t*)(g_wl + off) = pack_bf16x2(l0, l1);
    }
}

// ---------------------------------------------------------------------------
// u[i] = sum_e Wq[e,i]*bk[e];  v[i] = sum_e Wk[e,i]*bq[e];  c = bq.bk
// v2: grid 8 blocks x (64,4) threads; e split 4-way, smem-reduced.
// ---------------------------------------------------------------------------
__global__ __launch_bounds__(256) void bias_uvc(
    const float* __restrict__ Wq, const float* __restrict__ bq,
    const float* __restrict__ Wk, const float* __restrict__ bk)
{
    __shared__ float su[4][64];
    __shared__ float sv[4][64];
    __shared__ float scc[64];

    const int il = threadIdx.x;        // 0..63
    const int ec = threadIdx.y;        // 0..3
    const int i  = blockIdx.x * 64 + il;

    float u = 0.0f, v = 0.0f;
    const int e0 = ec * 128;
#pragma unroll 4
    for (int e = e0; e < e0 + 128; e++) {
        u = fmaf(Wq[(size_t)e * DD + i], bk[e], u);
        v = fmaf(Wk[(size_t)e * DD + i], bq[e], v);
    }
    su[ec][il] = u;
    sv[ec][il] = v;
    __syncthreads();

    if (ec == 0) {
        g_u[i] = su[0][il] + su[1][il] + su[2][il] + su[3][il];
        g_v[i] = sv[0][il] + sv[1][il] + sv[2][il] + sv[3][il];
    }

    if (blockIdx.x == 0) {
        if (ec == 1) {
            float s = 0.0f;
            for (int j = il; j < DD; j += 64) s = fmaf(bq[j], bk[j], s);
            scc[il] = s;
        }
        __syncthreads();
        if (ec == 0 && il == 0) {
            float s = 0.0f;
#pragma unroll
            for (int j = 0; j < 64; j++) s += scc[j];
            g_c = s;
        }
    }
}

// ---------------------------------------------------------------------------
// Convert kernels: fp32 -> bf16 hi/lo split
// ---------------------------------------------------------------------------
__global__ __launch_bounds__(256) void convert_x(const float* __restrict__ x)
{
    size_t i = (size_t)blockIdx.x * 256 + threadIdx.x;
    float4 v = ((const float4*)x)[i];
    __nv_bfloat16 h0 = __float2bfloat16_rn(v.x);
    __nv_bfloat16 h1 = __float2bfloat16_rn(v.y);
    __nv_bfloat16 h2 = __float2bfloat16_rn(v.z);
    __nv_bfloat16 h3 = __float2bfloat16_rn(v.w);
    __nv_bfloat16 l0 = __float2bfloat16_rn(v.x - __bfloat162float(h0));
    __nv_bfloat16 l1 = __float2bfloat16_rn(v.y - __bfloat162float(h1));
    __nv_bfloat16 l2 = __float2bfloat16_rn(v.z - __bfloat162float(h2));
    __nv_bfloat16 l3 = __float2bfloat16_rn(v.w - __bfloat162float(h3));
    ((uint2*)g_xh)[i] = make_uint2(pack_bf16x2(h0, h1), pack_bf16x2(h2, h3));
    ((uint2*)g_xl)[i] = make_uint2(pack_bf16x2(l0, l1), pack_bf16x2(l2, l3));
}

// Converts Wv into slot 1 of g_wh/g_wl.
__global__ __launch_bounds__(256) void convert_w(const float* __restrict__ Wv)
{
    size_t base = (size_t)(DD * DD / 4);
    size_t i = (size_t)blockIdx.x * 256 + threadIdx.x;
    float4 v = ((const float4*)Wv)[i];
    __nv_bfloat16 h0 = __float2bfloat16_rn(v.x);
    __nv_bfloat16 h1 = __float2bfloat16_rn(v.y);
    __nv_bfloat16 h2 = __float2bfloat16_rn(v.z);
    __nv_bfloat16 h3 = __float2bfloat16_rn(v.w);
    __nv_bfloat16 l0 = __float2bfloat16_rn(v.x - __bfloat162float(h0));
    __nv_bfloat16 l1 = __float2bfloat16_rn(v.y - __bfloat162float(h1));
    __nv_bfloat16 l2 = __float2bfloat16_rn(v.z - __bfloat162float(h2));
    __nv_bfloat16 l3 = __float2bfloat16_rn(v.w - __bfloat162float(h3));
    ((uint2*)g_wh)[base + i] = make_uint2(pack_bf16x2(h0, h1), pack_bf16x2(h2, h3));
    ((uint2*)g_wl)[base + i] = make_uint2(pack_bf16x2(l0, l1), pack_bf16x2(l2, l3));
}

// ---------------------------------------------------------------------------
// Z/V GEMM via mma.sync bf16 (split-fp32), R7 schedule (unchanged).
// z=0: Z = x*Gt^T (no bias); z=1: V = x*Wv^T + bv.
// CTA 128x128, 4 warps (2m x 2n), warp tile 64x64, 3-stage cp.async.
// grid = (4 n-tiles, 256 m-tiles, 2), 128 threads.
// ---------------------------------------------------------------------------
#define STAGE_BYTES 32768u   // A 16KB + B 16KB
#define SMEM_DYN (3 * STAGE_BYTES + 1024)

__global__ __launch_bounds__(128, 1) void qkv_mma(const float* __restrict__ bv)
{
    extern __shared__ __align__(16) char dsm[];
    const uint32_t raw  = smem_to_u32(dsm);
    const uint32_t base = (raw + 1023u) & ~1023u;

    const int tid  = threadIdx.x;
    const int wid  = tid >> 5;
    const int lane = tid & 31;
    const int wm   = wid & 1;
    const int wn   = wid >> 1;
    const int gid  = lane >> 2;
    const int tig  = lane & 3;

    const int z    = blockIdx.z;       // 0: Z, 1: V
    const int row0 = blockIdx.y * 128;
    const int col0 = blockIdx.x * 128;

    const __nv_bfloat16* whz = g_wh + (size_t)z * (DD * DD);
    const __nv_bfloat16* wlz = g_wl + (size_t)z * (DD * DD);

    uint32_t aAddr[4];
#pragma unroll
    for (int mf = 0; mf < 4; mf++) {
        int r = wm * 64 + mf * 16 + (lane & 15);
        uint32_t t = (uint32_t)((lane >> 4) * 16);
        aAddr[mf] = base + r * 128 + (t ^ ((uint32_t)(r & 7) * 16));
    }
    uint32_t bAddr[4];
#pragma unroll
    for (int bh = 0; bh < 4; bh++) {
        int n = wn * 64 + bh * 16 + (lane & 7) + ((lane >> 4) & 1) * 8;
        uint32_t t = (uint32_t)(((lane >> 3) & 1) * 16);
        bAddr[bh] = base + 16384u + n * 128 + (t ^ ((uint32_t)(n & 7) * 16));
    }

    float c[4][8][4];
#pragma unroll
    for (int mf = 0; mf < 4; mf++)
#pragma unroll
        for (int nf = 0; nf < 8; nf++)
#pragma unroll
            for (int q = 0; q < 4; q++) c[mf][nf][q] = 0.0f;

    auto issue_chunk = [&](int ci, int s) {
        const __nv_bfloat16* Asrc = (ci < 16) ? g_xh : g_xl;
        const __nv_bfloat16* Bsrc = (ci >= 8 && ci < 16) ? wlz : whz;
        const int koff = (ci & 7) * 64;
        const uint32_t stage = base + (uint32_t)s * STAGE_BYTES;
#pragma unroll
        for (int j = 0; j < 8; j++) {
            int idx = tid + j * 128;
            int r = idx >> 3, o = idx & 7;
            uint32_t bo = (uint32_t)(r * 128 + o * 16);
            cp_async16(stage + SMEM_SWIZZLE_128B(bo),
                       Asrc + (size_t)(row0 + r) * DD + koff + o * 8);
        }
#pragma unroll
        for (int j = 0; j < 8; j++) {
            int idx = tid + j * 128;
            int n = idx >> 3, o = idx & 7;
            uint32_t bo = (uint32_t)(n * 128 + o * 16);
            cp_async16(stage + 16384u + SMEM_SWIZZLE_128B(bo),
                       Bsrc + (size_t)(col0 + n) * DD + koff + o * 8);
        }
        cp_commit();
    };

    issue_chunk(0, 0);
    issue_chunk(1, 1);

    for (int ck = 0; ck < 24; ck++) {
        if (ck + 2 < 24) issue_chunk(ck + 2, (ck + 2) % 3);
        if (ck < 22) cp_wait2();
        else if (ck == 22) cp_wait1();
        else cp_wait0();
        __syncthreads();

        const uint32_t soff = (uint32_t)(ck % 3) * STAGE_BYTES;
#pragma unroll
        for (int kk = 0; kk < 4; kk++) {
            const uint32_t kx = (uint32_t)(kk << 5);
            uint32_t a[4][4];
#pragma unroll
            for (int mf = 0; mf < 4; mf++)
                ldmatrix_x4(a[mf][0], a[mf][1], a[mf][2], a[mf][3],
                            (aAddr[mf] + soff) ^ kx);
            uint32_t b[8][2];
#pragma unroll
            for (int bh = 0; bh < 4; bh++) {
                uint32_t r0, r1, r2, r3;
                ldmatrix_x4(r0, r1, r2, r3, (bAddr[bh] + soff) ^ kx);
                b[bh * 2 + 0][0] = r0; b[bh * 2 + 0][1] = r1;
                b[bh * 2 + 1][0] = r2; b[bh * 2 + 1][1] = r3;
            }
#pragma unroll
            for (int mf = 0; mf < 4; mf++)
#pragma unroll
                for (int nf = 0; nf < 8; nf++)
                    mma_16816(c[mf][nf][0], c[mf][nf][1], c[mf][nf][2], c[mf][nf][3],
                              a[mf][0], a[mf][1], a[mf][2], a[mf][3],
                              b[nf][0], b[nf][1]);
        }
        __syncthreads();
    }

    float* out = (z == 0) ? g_Z : g_V;

#pragma unroll
    for (int nf = 0; nf < 8; nf++) {
        const int col = col0 + wn * 64 + nf * 8 + tig * 2;
        float2 bb = (z == 1) ? *(const float2*)(bv + col) : make_float2(0.0f, 0.0f);
#pragma unroll
        for (int mf = 0; mf < 4; mf++) {
            const int r0 = row0 + wm * 64 + mf * 16 + gid;
            float2 v0 = make_float2(c[mf][nf][0] + bb.x, c[mf][nf][1] + bb.y);
            float2 v1 = make_float2(c[mf][nf][2] + bb.x, c[mf][nf][3] + bb.y);
            *(float2*)(out + (size_t)r0 * DD + col)       = v0;
            *(float2*)(out + (size_t)(r0 + 8) * DD + col) = v1;
        }
    }
}

// ---------------------------------------------------------------------------
// Kernel 2: scores + softmax.
// score[m,k] = (Sum_b Sum_d Z[b,m,d]*x[b,k,d] + P[m] + R[k] + 4c) * scale
// ---------------------------------------------------------------------------
__global__ __launch_bounds__(256) void score_softmax(const float* __restrict__ x)
{
    __shared__ float sQ[4096];        // Z rows   [4b][8][128]
    __shared__ float sK[4096];        // x rows   [4b][8][128]
    __shared__ float part[64 * 65];
    __shared__ float Pp[4][8][9];
    __shared__ float Rp[4][8][9];
    __shared__ float PP[8], RR[8];
    __shared__ float sc[64];
    __shared__ float es[64];

    const int tn  = blockIdx.x;
    const int tid = threadIdx.x;
    const int b    = tid >> 6;
    const int r    = tid & 63;
    const int tile = r >> 4;
    const int slc  = r & 15;
    const int mt   = tile >> 1;
    const int kt   = tile & 1;

    const int pb   = tid >> 6;
    const int prow = (tid >> 3) & 7;
    const int ps8  = tid & 7;

    float acc[4][4];
#pragma unroll
    for (int i = 0; i < 4; i++)
#pragma unroll
        for (int j = 0; j < 4; j++) acc[i][j] = 0.0f;
    float pr = 0.0f, rr = 0.0f;

    const float4* Z4 = (const float4*)g_Z;
    const float4* X4 = (const float4*)x;
    const float4* u4 = (const float4*)g_u;
    const float4* v4 = (const float4*)g_v;

    for (int ch = 0; ch < 4; ch++) {
        __syncthreads();
#pragma unroll
        for (int j = 0; j < 4; j++) {
            int idx = tid + j * 256;
            int lb = idx >> 8, lrr = (idx >> 5) & 7, o = idx & 31;
            size_t grow = (size_t)lb * TNM + (size_t)tn * MM + lrr;
            ((float4*)sQ)[(lb * 8 + lrr) * 32 + o] = Z4[grow * (DD / 4) + ch * 32 + o];
            ((float4*)sK)[(lb * 8 + lrr) * 32 + o] = X4[grow * (DD / 4) + ch * 32 + o];
        }
        __syncthreads();

#pragma unroll
        for (int j = 0; j < 2; j++) {
            const int d4 = j * 16 + slc;
            float4 qf[4], kf[4];
#pragma unroll
            for (int i = 0; i < 4; i++)
                qf[i] = ((const float4*)sQ)[(b * 8 + mt * 4 + i) * 32 + d4];
#pragma unroll
            for (int i = 0; i < 4; i++)
                kf[i] = ((const float4*)sK)[(b * 8 + kt * 4 + i) * 32 + d4];
#pragma unroll
            for (int i = 0; i < 4; i++)
#pragma unroll
                for (int kx = 0; kx < 4; kx++) {
                    acc[i][kx] = fmaf(qf[i].x, kf[kx].x, acc[i][kx]);
                    acc[i][kx] = fmaf(qf[i].y, kf[kx].y, acc[i][kx]);
                    acc[i][kx] = fmaf(qf[i].z, kf[kx].z, acc[i][kx]);
                    acc[i][kx] = fmaf(qf[i].w, kf[kx].w, acc[i][kx]);
                }
        }

#pragma unroll
        for (int w = 0; w < 4; w++) {
            float4 xv = ((const float4*)sK)[(pb * 8 + prow) * 32 + ps8 * 4 + w];
            float4 uu = u4[ch * 32 + ps8 * 4 + w];
            float4 vv = v4[ch * 32 + ps8 * 4 + w];
            pr = fmaf(xv.x, uu.x, pr); pr = fmaf(xv.y, uu.y, pr);
            pr = fmaf(xv.z, uu.z, pr); pr = fmaf(xv.w, uu.w, pr);
            rr = fmaf(xv.x, vv.x, rr); rr = fmaf(xv.y, vv.y, rr);
            rr = fmaf(xv.z, vv.z, rr); rr = fmaf(xv.w, vv.w, rr);
        }
    }

    const int h = b * 16 + slc;
#pragma unroll
    for (int i = 0; i < 4; i++)
#pragma unroll
        for (int kx = 0; kx < 4; kx++) {
            int pair = (mt * 4 + i) * 8 + (kt * 4 + kx);
            part[h * 65 + pair] = acc[i][kx];
        }
    Pp[pb][prow][ps8] = pr;
    Rp[pb][prow][ps8] = rr;
    __syncthreads();

    if (tid < 8) {
        float s = 0.0f;
#pragma unroll
        for (int bb = 0; bb < 4; bb++)
#pragma unroll
            for (int ss = 0; ss < 8; ss++) s += Pp[bb][tid][ss];
        PP[tid] = s;
    } else if (tid < 16) {
        const int m = tid - 8;
        float s = 0.0f;
#pragma unroll
        for (int bb = 0; bb < 4; bb++)
#pragma unroll
            for (int ss = 0; ss < 8; ss++) s += Rp[bb][m][ss];
        RR[m] = s;
    }
    __syncthreads();

    if (tid < 64) {
        float s = 0.0f;
#pragma unroll
        for (int i = 0; i < 64; i++) s += part[i * 65 + tid];
        const int m = tid >> 3, k = tid & 7;
        sc[tid] = (s + PP[m] + RR[k] + 4.0f * g_c) * 0.04419417382415922f;
    }
    __syncthreads();

    if (tid < 64) {
        const int m = tid >> 3;
        float mx = sc[m * 8];
#pragma unroll
        for (int j = 1; j < 8; j++) mx = fmaxf(mx, sc[m * 8 + j]);
        es[tid] = expf(sc[tid] - mx);
    }
    __syncthreads();

    if (tid < 64) {
        const int m = tid >> 3;
        float sum = 0.0f;
#pragma unroll
        for (int j = 0; j < 8; j++) sum += es[m * 8 + j];
        g_W[tn * 64 + tid] = es[tid] / sum;
    }
}

// ---------------------------------------------------------------------------
// Kernel 3: weighted V sum
// ---------------------------------------------------------------------------
__global__ __launch_bounds__(256) void out_kernel(float* __restrict__ out)
{
    const int btn = blockIdx.x;
    const int tid = threadIdx.x;
    const int d4  = tid & 127;
    const int mh  = tid >> 7;
    const int tn  = btn % (TT * NN);

    __shared__ float w[64];
    if (tid < 64) w[tid] = g_W[tn * 64 + tid];
    __syncthreads();

    const float4* V4 = (const float4*)(g_V + (size_t)btn * MM * DD);
    float4* O4 = (float4*)(out + (size_t)btn * MM * DD);

    float4 acc[4];
#pragma unroll
    for (int i = 0; i < 4; i++) acc[i] = make_float4(0.f, 0.f, 0.f, 0.f);

#pragma unroll
    for (int k = 0; k < 8; k++) {
        float4 v = V4[k * (DD / 4) + d4];
#pragma unroll
        for (int i = 0; i < 4; i++) {
            float wm = w[(mh * 4 + i) * 8 + k];
            acc[i].x = fmaf(wm, v.x, acc[i].x);
            acc[i].y = fmaf(wm, v.y, acc[i].y);
            acc[i].z = fmaf(wm, v.z, acc[i].z);
            acc[i].w = fmaf(wm, v.w, acc[i].w);
        }
    }

#pragma unroll
    for (int i = 0; i < 4; i++) {
        O4[(mh * 4 + i) * (DD / 4) + d4] = acc[i];
    }
}

// ---------------------------------------------------------------------------
extern "C" void kernel_launch(void* const* d_in, const int* in_sizes, int n_in,
                              void* d_out, int out_size)
{
    const float* x  = (const float*)d_in[0];
    const float* Wq = (const float*)d_in[1];
    const float* bq = (const float*)d_in[2];
    const float* Wk = (const float*)d_in[3];
    const float* bk = (const float*)d_in[4];
    const float* Wv = (const float*)d_in[5];
    const float* bv = (const float*)d_in[6];

    cudaFuncSetAttribute(qkv_mma, cudaFuncAttributeMaxDynamicSharedMemorySize, SMEM_DYN);

    convert_x<<<(ROWS * DD / 4) / 256, 256>>>(x);
    gemm_G<<<dim3(16, 16), 256>>>(Wq, Wk);
    bias_uvc<<<8, dim3(64, 4)>>>(Wq, bq, Wk, bk);
    convert_w<<<(DD * DD / 4) / 256, 256>>>(Wv);
    qkv_mma<<<dim3(4, ROWS / 128, 2), 128, SMEM_DYN>>>(bv);
    score_softmax<<<TT * NN, 256>>>(x);
    out_kernel<<<BB * TT * NN, 256>>>((float*)d_out);
}

// round 13
// speedup vs baseline: 4.5058x; 1.0406x over previous
#include <cuda_runtime.h>
#include <cuda_bf16.h>
#include <cstdint>

// Problem dims
#define BB 4
#define TT 64
#define NN 16
#define MM 8
#define DD 512
#define ROWS (BB * TT * NN * MM)   // 32768 flattened (b,t,n,m) rows
#define TNM  (TT * NN * MM)

// ---------------------------------------------------------------------------
// Scratch (__device__ globals; allocation-free rule)
// ---------------------------------------------------------------------------
__device__ float g_Z[(size_t)ROWS * DD];     // Z = x * (Wq^T Wk)
__device__ float g_V[(size_t)ROWS * DD];
__device__ float g_u[DD];                    // Wq^T bk
__device__ float g_v[DD];                    // Wk^T bq
__device__ float g_c;                        // bq . bk

__device__ __align__(16) __nv_bfloat16 g_xh[(size_t)ROWS * DD];
__device__ __align__(16) __nv_bfloat16 g_xl[(size_t)ROWS * DD];
__device__ __align__(16) __nv_bfloat16 g_wh[2 * DD * DD];   // z=0: Gt, z=1: Wv
__device__ __align__(16) __nv_bfloat16 g_wl[2 * DD * DD];

// ---------------------------------------------------------------------------
// Helpers
// ---------------------------------------------------------------------------
__device__ __forceinline__ uint32_t smem_to_u32(const void* smem_ptr) {
    uint32_t addr;
    asm("{ .reg .u64 tmp; cvta.to.shared.u64 tmp, %1; cvt.u32.u64 %0, tmp; }"
        : "=r"(addr) : "l"(smem_ptr));
    return addr;
}

#define SMEM_SWIZZLE_128B(byte_offset) \
    ((byte_offset) ^ (((byte_offset) >> 3) & 0x70))

__device__ __forceinline__ void cp_async16(uint32_t dst, const void* src) {
    asm volatile("cp.async.cg.shared.global [%0], [%1], 16;"
                 :: "r"(dst), "l"(src) : "memory");
}
__device__ __forceinline__ void cp_commit() {
    asm volatile("cp.async.commit_group;" ::: "memory");
}
__device__ __forceinline__ void cp_wait1() {
    asm volatile("cp.async.wait_group 1;" ::: "memory");
}
__device__ __forceinline__ void cp_wait0() {
    asm volatile("cp.async.wait_group 0;" ::: "memory");
}

__device__ __forceinline__ void ldmatrix_x4(
    uint32_t& r0, uint32_t& r1, uint32_t& r2, uint32_t& r3, uint32_t addr)
{
    asm volatile("ldmatrix.sync.aligned.m8n8.x4.shared.b16 {%0,%1,%2,%3}, [%4];"
                 : "=r"(r0), "=r"(r1), "=r"(r2), "=r"(r3) : "r"(addr));
}

__device__ __forceinline__ void mma_16816(
    float& c0, float& c1, float& c2, float& c3,
    uint32_t a0, uint32_t a1, uint32_t a2, uint32_t a3,
    uint32_t b0, uint32_t b1)
{
    asm volatile(
        "mma.sync.aligned.m16n8k16.row.col.f32.bf16.bf16.f32 "
        "{%0,%1,%2,%3}, {%4,%5,%6,%7}, {%8,%9}, {%0,%1,%2,%3};"
        : "+f"(c0), "+f"(c1), "+f"(c2), "+f"(c3)
        : "r"(a0), "r"(a1), "r"(a2), "r"(a3), "r"(b0), "r"(b1));
}

__device__ __forceinline__ uint32_t pack_bf16x2(__nv_bfloat16 a, __nv_bfloat16 b) {
    return (uint32_t)__bfloat16_as_ushort(a) | ((uint32_t)__bfloat16_as_ushort(b) << 16);
}

// ---------------------------------------------------------------------------
// Convert x: fp32 -> bf16 hi/lo split
// ---------------------------------------------------------------------------
__global__ __launch_bounds__(256) void convert_x(const float* __restrict__ x)
{
    size_t i = (size_t)blockIdx.x * 256 + threadIdx.x;
    float4 v = ((const float4*)x)[i];
    __nv_bfloat16 h0 = __float2bfloat16_rn(v.x);
    __nv_bfloat16 h1 = __float2bfloat16_rn(v.y);
    __nv_bfloat16 h2 = __float2bfloat16_rn(v.z);
    __nv_bfloat16 h3 = __float2bfloat16_rn(v.w);
    __nv_bfloat16 l0 = __float2bfloat16_rn(v.x - __bfloat162float(h0));
    __nv_bfloat16 l1 = __float2bfloat16_rn(v.y - __bfloat162float(h1));
    __nv_bfloat16 l2 = __float2bfloat16_rn(v.z - __bfloat162float(h2));
    __nv_bfloat16 l3 = __float2bfloat16_rn(v.w - __bfloat162float(h3));
    ((uint2*)g_xh)[i] = make_uint2(pack_bf16x2(h0, h1), pack_bf16x2(h2, h3));
    ((uint2*)g_xl)[i] = make_uint2(pack_bf16x2(l0, l1), pack_bf16x2(l2, l3));
}

// ---------------------------------------------------------------------------
// prep_w: fused weight prework, one launch, 520 blocks x 256 threads.
//   blocks [0,256):   Gt[j,i] = sum_e Wk[e,j]*Wq[e,i] -> bf16 hi/lo slot 0
//   blocks [256,512): convert Wv -> bf16 hi/lo slot 1
//   blocks [512,520): u/v/c bias precompute
// ---------------------------------------------------------------------------
__global__ __launch_bounds__(256) void prep_w(
    const float* __restrict__ Wq, const float* __restrict__ bq,
    const float* __restrict__ Wk, const float* __restrict__ bk,
    const float* __restrict__ Wv)
{
    __shared__ float Ak[16][36];
    __shared__ float Bk[16][36];
    __shared__ float su[4][64];
    __shared__ float sv[4][64];
    __shared__ float scc[64];

    const int bx  = blockIdx.x;
    const int tid = threadIdx.x;

    if (bx < 256) {
        // --- gemm_G: 32x32 tile, 2x2 microtile ---
        const int j0 = (bx >> 4) * 32;
        const int i0 = (bx & 15) * 32;
        const int le = tid >> 4;
        const int lc = (tid & 15) * 2;
        const int ty = tid >> 4;
        const int tx = tid & 15;

        float acc[2][2] = {{0.0f, 0.0f}, {0.0f, 0.0f}};

        for (int e0 = 0; e0 < DD; e0 += 16) {
            __syncthreads();
            *(float2*)&Ak[le][lc] = *(const float2*)(Wk + (size_t)(e0 + le) * DD + j0 + lc);
            *(float2*)&Bk[le][lc] = *(const float2*)(Wq + (size_t)(e0 + le) * DD + i0 + lc);
            __syncthreads();
#pragma unroll
            for (int e = 0; e < 16; e++) {
                float a0 = Ak[e][ty * 2], a1 = Ak[e][ty * 2 + 1];
                float b0 = Bk[e][tx * 2], b1 = Bk[e][tx * 2 + 1];
                acc[0][0] = fmaf(a0, b0, acc[0][0]);
                acc[0][1] = fmaf(a0, b1, acc[0][1]);
                acc[1][0] = fmaf(a1, b0, acc[1][0]);
                acc[1][1] = fmaf(a1, b1, acc[1][1]);
            }
        }

#pragma unroll
        for (int a = 0; a < 2; a++) {
            const int j = j0 + ty * 2 + a;
            const size_t off = (size_t)j * DD + i0 + tx * 2;
            __nv_bfloat16 h0 = __float2bfloat16_rn(acc[a][0]);
            __nv_bfloat16 h1 = __float2bfloat16_rn(acc[a][1]);
            __nv_bfloat16 l0 = __float2bfloat16_rn(acc[a][0] - __bfloat162float(h0));
            __nv_bfloat16 l1 = __float2bfloat16_rn(acc[a][1] - __bfloat162float(h1));
            *(uint32_t*)(g_wh + off) = pack_bf16x2(h0, h1);
            *(uint32_t*)(g_wl + off) = pack_bf16x2(l0, l1);
        }
    } else if (bx < 512) {
        // --- convert Wv into slot 1 ---
        size_t base = (size_t)(DD * DD / 4);
        size_t i = (size_t)(bx - 256) * 256 + tid;
        float4 v = ((const float4*)Wv)[i];
        __nv_bfloat16 h0 = __float2bfloat16_rn(v.x);
        __nv_bfloat16 h1 = __float2bfloat16_rn(v.y);
        __nv_bfloat16 h2 = __float2bfloat16_rn(v.z);
        __nv_bfloat16 h3 = __float2bfloat16_rn(v.w);
        __nv_bfloat16 l0 = __float2bfloat16_rn(v.x - __bfloat162float(h0));
        __nv_bfloat16 l1 = __float2bfloat16_rn(v.y - __bfloat162float(h1));
        __nv_bfloat16 l2 = __float2bfloat16_rn(v.z - __bfloat162float(h2));
        __nv_bfloat16 l3 = __float2bfloat16_rn(v.w - __bfloat162float(h3));
        ((uint2*)g_wh)[base + i] = make_uint2(pack_bf16x2(h0, h1), pack_bf16x2(h2, h3));
        ((uint2*)g_wl)[base + i] = make_uint2(pack_bf16x2(l0, l1), pack_bf16x2(l2, l3));
    } else {
        // --- bias u/v/c: 8 blocks of (64 i-lanes x 4 e-chunks) ---
        const int blk = bx - 512;
        const int il  = tid & 63;
        const int ec  = tid >> 6;
        const int i   = blk * 64 + il;

        float u = 0.0f, v = 0.0f;
        const int e0 = ec * 128;
#pragma unroll 4
        for (int e = e0; e < e0 + 128; e++) {
            u = fmaf(Wq[(size_t)e * DD + i], bk[e], u);
            v = fmaf(Wk[(size_t)e * DD + i], bq[e], v);
        }
        su[ec][il] = u;
        sv[ec][il] = v;
        __syncthreads();

        if (ec == 0) {
            g_u[i] = su[0][il] + su[1][il] + su[2][il] + su[3][il];
            g_v[i] = sv[0][il] + sv[1][il] + sv[2][il] + sv[3][il];
        }

        if (blk == 0) {
            if (ec == 1) {
                float s = 0.0f;
                for (int j = il; j < DD; j += 64) s = fmaf(bq[j], bk[j], s);
                scc[il] = s;
            }
            __syncthreads();
            if (ec == 0 && il == 0) {
                float s = 0.0f;
#pragma unroll
                for (int j = 0; j < 64; j++) s += scc[j];
                g_c = s;
            }
        }
    }
}

// ---------------------------------------------------------------------------
// Z/V GEMM via mma.sync bf16 (split-fp32), R7 shape + single-sync pipeline.
// z=0: Z = x*Gt^T (no bias); z=1: V = x*Wv^T + bv.
// CTA 128x128, 4 warps (2m x 2n), warp tile 64x64, 3-stage cp.async.
// Loop order: wait -> sync -> prefetch(ck+2) -> compute. The prefetch writes
// stage (ck-1)%3 which the barrier just drained, so no trailing sync needed.
// grid = (4 n-tiles, 256 m-tiles, 2), 128 threads.
// ---------------------------------------------------------------------------
#define STAGE_BYTES 32768u   // A 16KB + B 16KB
#define SMEM_DYN (3 * STAGE_BYTES + 1024)

__global__ __launch_bounds__(128, 1) void qkv_mma(const float* __restrict__ bv)
{
    extern __shared__ __align__(16) char dsm[];
    const uint32_t raw  = smem_to_u32(dsm);
    const uint32_t base = (raw + 1023u) & ~1023u;

    const int tid  = threadIdx.x;
    const int wid  = tid >> 5;
    const int lane = tid & 31;
    const int wm   = wid & 1;
    const int wn   = wid >> 1;
    const int gid  = lane >> 2;
    const int tig  = lane & 3;

    const int z    = blockIdx.z;       // 0: Z, 1: V
    const int row0 = blockIdx.y * 128;
    const int col0 = blockIdx.x * 128;

    const __nv_bfloat16* whz = g_wh + (size_t)z * (DD * DD);
    const __nv_bfloat16* wlz = g_wl + (size_t)z * (DD * DD);

    uint32_t aAddr[4];
#pragma unroll
    for (int mf = 0; mf < 4; mf++) {
        int r = wm * 64 + mf * 16 + (lane & 15);
        uint32_t t = (uint32_t)((lane >> 4) * 16);
        aAddr[mf] = base + r * 128 + (t ^ ((uint32_t)(r & 7) * 16));
    }
    uint32_t bAddr[4];
#pragma unroll
    for (int bh = 0; bh < 4; bh++) {
        int n = wn * 64 + bh * 16 + (lane & 7) + ((lane >> 4) & 1) * 8;
        uint32_t t = (uint32_t)(((lane >> 3) & 1) * 16);
        bAddr[bh] = base + 16384u + n * 128 + (t ^ ((uint32_t)(n & 7) * 16));
    }

    float c[4][8][4];
#pragma unroll
    for (int mf = 0; mf < 4; mf++)
#pragma unroll
        for (int nf = 0; nf < 8; nf++)
#pragma unroll
            for (int q = 0; q < 4; q++) c[mf][nf][q] = 0.0f;

    auto issue_chunk = [&](int ci, int s) {
        const __nv_bfloat16* Asrc = (ci < 16) ? g_xh : g_xl;
        const __nv_bfloat16* Bsrc = (ci >= 8 && ci < 16) ? wlz : whz;
        const int koff = (ci & 7) * 64;
        const uint32_t stage = base + (uint32_t)s * STAGE_BYTES;
#pragma unroll
        for (int j = 0; j < 8; j++) {
            int idx = tid + j * 128;
            int r = idx >> 3, o = idx & 7;
            uint32_t bo = (uint32_t)(r * 128 + o * 16);
            cp_async16(stage + SMEM_SWIZZLE_128B(bo),
                       Asrc + (size_t)(row0 + r) * DD + koff + o * 8);
        }
#pragma unroll
        for (int j = 0; j < 8; j++) {
            int idx = tid + j * 128;
            int n = idx >> 3, o = idx & 7;
            uint32_t bo = (uint32_t)(n * 128 + o * 16);
            cp_async16(stage + 16384u + SMEM_SWIZZLE_128B(bo),
                       Bsrc + (size_t)(col0 + n) * DD + koff + o * 8);
        }
        cp_commit();
    };

    issue_chunk(0, 0);
    issue_chunk(1, 1);

    for (int ck = 0; ck < 24; ck++) {
        if (ck < 23) cp_wait1(); else cp_wait0();
        __syncthreads();
        if (ck + 2 < 24) issue_chunk(ck + 2, (ck + 2) % 3);

        const uint32_t soff = (uint32_t)(ck % 3) * STAGE_BYTES;
#pragma unroll
        for (int kk = 0; kk < 4; kk++) {
            const uint32_t kx = (uint32_t)(kk << 5);
            uint32_t a[4][4];
#pragma unroll
            for (int mf = 0; mf < 4; mf++)
                ldmatrix_x4(a[mf][0], a[mf][1], a[mf][2], a[mf][3],
                            (aAddr[mf] + soff) ^ kx);
            uint32_t b[8][2];
#pragma unroll
            for (int bh = 0; bh < 4; bh++) {
                uint32_t r0, r1, r2, r3;
                ldmatrix_x4(r0, r1, r2, r3, (bAddr[bh] + soff) ^ kx);
                b[bh * 2 + 0][0] = r0; b[bh * 2 + 0][1] = r1;
                b[bh * 2 + 1][0] = r2; b[bh * 2 + 1][1] = r3;
            }
#pragma unroll
            for (int mf = 0; mf < 4; mf++)
#pragma unroll
                for (int nf = 0; nf < 8; nf++)
                    mma_16816(c[mf][nf][0], c[mf][nf][1], c[mf][nf][2], c[mf][nf][3],
                              a[mf][0], a[mf][1], a[mf][2], a[mf][3],
                              b[nf][0], b[nf][1]);
        }
    }

    float* out = (z == 0) ? g_Z : g_V;

#pragma unroll
    for (int nf = 0; nf < 8; nf++) {
        const int col = col0 + wn * 64 + nf * 8 + tig * 2;
        float2 bb = (z == 1) ? *(const float2*)(bv + col) : make_float2(0.0f, 0.0f);
#pragma unroll
        for (int mf = 0; mf < 4; mf++) {
            const int r0 = row0 + wm * 64 + mf * 16 + gid;
            float2 v0 = make_float2(c[mf][nf][0] + bb.x, c[mf][nf][1] + bb.y);
            float2 v1 = make_float2(c[mf][nf][2] + bb.x, c[mf][nf][3] + bb.y);
            *(float2*)(out + (size_t)r0 * DD + col)       = v0;
            *(float2*)(out + (size_t)(r0 + 8) * DD + col) = v1;
        }
    }
}

// ---------------------------------------------------------------------------
// score_out: scores + softmax + weighted-V output, fused.
// score[m,k] = (Sum_b Sum_d Z[b,m,d]*x[b,k,d] + P[m] + R[k] + 4c) * scale
// Then out[b,t,n,m,:] = Sum_k w[m,k] * V[b,t,n,k,:] streamed directly.
// One block per (t,n), 256 threads.
// ---------------------------------------------------------------------------
__global__ __launch_bounds__(256) void score_out(
    const float* __restrict__ x, float* __restrict__ out)
{
    __shared__ float sQ[4096];        // Z rows   [4b][8][128]
    __shared__ float sK[4096];        // x rows   [4b][8][128]
    __shared__ float part[64 * 65];
    __shared__ float red[4][64];
    __shared__ float Pp[4][8][9];
    __shared__ float Rp[4][8][9];
    __shared__ float PP[8], RR[8];
    __shared__ float sc[64];
    __shared__ float es[64];
    __shared__ float w[64];

    const int tn  = blockIdx.x;
    const int tid = threadIdx.x;
    const int b    = tid >> 6;
    const int r    = tid & 63;
    const int tile = r >> 4;
    const int slc  = r & 15;
    const int mt   = tile >> 1;
    const int kt   = tile & 1;

    const int pb   = tid >> 6;
    const int prow = (tid >> 3) & 7;
    const int ps8  = tid & 7;

    float acc[4][4];
#pragma unroll
    for (int i = 0; i < 4; i++)
#pragma unroll
        for (int j = 0; j < 4; j++) acc[i][j] = 0.0f;
    float pr = 0.0f, rr = 0.0f;

    const float4* Z4 = (const float4*)g_Z;
    const float4* X4 = (const float4*)x;
    const float4* u4 = (const float4*)g_u;
    const float4* v4 = (const float4*)g_v;

    for (int ch = 0; ch < 4; ch++) {
        __syncthreads();
#pragma unroll
        for (int j = 0; j < 4; j++) {
            int idx = tid + j * 256;
            int lb = idx >> 8, lrr = (idx >> 5) & 7, o = idx & 31;
            size_t grow = (size_t)lb * TNM + (size_t)tn * MM + lrr;
            ((float4*)sQ)[(lb * 8 + lrr) * 32 + o] = Z4[grow * (DD / 4) + ch * 32 + o];
            ((float4*)sK)[(lb * 8 + lrr) * 32 + o] = X4[grow * (DD / 4) + ch * 32 + o];
        }
        __syncthreads();

#pragma unroll
        for (int j = 0; j < 2; j++) {
            const int d4 = j * 16 + slc;
            float4 qf[4], kf[4];
#pragma unroll
            for (int i = 0; i < 4; i++)
                qf[i] = ((const float4*)sQ)[(b * 8 + mt * 4 + i) * 32 + d4];
#pragma unroll
            for (int i = 0; i < 4; i++)
                kf[i] = ((const float4*)sK)[(b * 8 + kt * 4 + i) * 32 + d4];
#pragma unroll
            for (int i = 0; i < 4; i++)
#pragma unroll
                for (int kx = 0; kx < 4; kx++) {
                    acc[i][kx] = fmaf(qf[i].x, kf[kx].x, acc[i][kx]);
                    acc[i][kx] = fmaf(qf[i].y, kf[kx].y, acc[i][kx]);
                    acc[i][kx] = fmaf(qf[i].z, kf[kx].z, acc[i][kx]);
                    acc[i][kx] = fmaf(qf[i].w, kf[kx].w, acc[i][kx]);
                }
        }

#pragma unroll
        for (int ww = 0; ww < 4; ww++) {
            float4 xv = ((const float4*)sK)[(pb * 8 + prow) * 32 + ps8 * 4 + ww];
            float4 uu = u4[ch * 32 + ps8 * 4 + ww];
            float4 vv = v4[ch * 32 + ps8 * 4 + ww];
            pr = fmaf(xv.x, uu.x, pr); pr = fmaf(xv.y, uu.y, pr);
            pr = fmaf(xv.z, uu.z, pr); pr = fmaf(xv.w, uu.w, pr);
            rr = fmaf(xv.x, vv.x, rr); rr = fmaf(xv.y, vv.y, rr);
            rr = fmaf(xv.z, vv.z, rr); rr = fmaf(xv.w, vv.w, rr);
        }
    }

    const int h = b * 16 + slc;
#pragma unroll
    for (int i = 0; i < 4; i++)
#pragma unroll
        for (int kx = 0; kx < 4; kx++) {
            int pair = (mt * 4 + i) * 8 + (kt * 4 + kx);
            part[h * 65 + pair] = acc[i][kx];
        }
    Pp[pb][prow][ps8] = pr;
    Rp[pb][prow][ps8] = rr;
    __syncthreads();

    // Parallel partial reduction: 256 threads, each sums 16 of 64 h-slices.
    {
        const int pair = tid & 63;
        const int q    = tid >> 6;
        float s = 0.0f;
#pragma unroll
        for (int hh = q * 16; hh < q * 16 + 16; hh++) s += part[hh * 65 + pair];
        red[q][pair] = s;
    }
    if (tid < 8) {
        float s = 0.0f;
#pragma unroll
        for (int bb = 0; bb < 4; bb++)
#pragma unroll
            for (int ss = 0; ss < 8; ss++) s += Pp[bb][tid][ss];
        PP[tid] = s;
    } else if (tid < 16) {
        const int m = tid - 8;
        float s = 0.0f;
#pragma unroll
        for (int bb = 0; bb < 4; bb++)
#pragma unroll
            for (int ss = 0; ss < 8; ss++) s += Rp[bb][m][ss];
        RR[m] = s;
    }
    __syncthreads();

    if (tid < 64) {
        float s = red[0][tid] + red[1][tid] + red[2][tid] + red[3][tid];
        const int m = tid >> 3, k = tid & 7;
        sc[tid] = (s + PP[m] + RR[k] + 4.0f * g_c) * 0.04419417382415922f;
    }
    __syncthreads();

    if (tid < 64) {
        const int m = tid >> 3;
        float mx = sc[m * 8];
#pragma unroll
        for (int j = 1; j < 8; j++) mx = fmaxf(mx, sc[m * 8 + j]);
        es[tid] = expf(sc[tid] - mx);
    }
    __syncthreads();

    if (tid < 64) {
        const int m = tid >> 3;
        float sum = 0.0f;
#pragma unroll
        for (int j = 0; j < 8; j++) sum += es[m * 8 + j];
        w[tid] = es[tid] / sum;
    }
    __syncthreads();

    // ---- Phase 2: out[b,m,:] = sum_k w[m,k] * V[b,k,:] for all 4 b ----
    const int d4 = tid & 127;
    const int mh = tid >> 7;      // m in [mh*4, mh*4+4)

#pragma unroll 1
    for (int bb = 0; bb < BB; bb++) {
        const size_t btn = (size_t)bb * (TT * NN) + tn;
        const float4* V4 = (const float4*)(g_V + btn * MM * DD);
        float4* O4 = (float4*)(out + btn * MM * DD);

        float4 oacc[4];
#pragma unroll
        for (int i = 0; i < 4; i++) oacc[i] = make_float4(0.f, 0.f, 0.f, 0.f);

#pragma unroll
        for (int k = 0; k < 8; k++) {
            float4 vv = V4[k * (DD / 4) + d4];
#pragma unroll
            for (int i = 0; i < 4; i++) {
                float wm = w[(mh * 4 + i) * 8 + k];
                oacc[i].x = fmaf(wm, vv.x, oacc[i].x);
                oacc[i].y = fmaf(wm, vv.y, oacc[i].y);
                oacc[i].z = fmaf(wm, vv.z, oacc[i].z);
                oacc[i].w = fmaf(wm, vv.w, oacc[i].w);
            }
        }

#pragma unroll
        for (int i = 0; i < 4; i++)
            O4[(mh * 4 + i) * (DD / 4) + d4] = oacc[i];
    }
}

// ---------------------------------------------------------------------------
extern "C" void kernel_launch(void* const* d_in, const int* in_sizes, int n_in,
                              void* d_out, int out_size)
{
    const float* x  = (const float*)d_in[0];
    const float* Wq = (const float*)d_in[1];
    const float* bq = (const float*)d_in[2];
    const float* Wk = (const float*)d_in[3];
    const float* bk = (const float*)d_in[4];
    const float* Wv = (const float*)d_in[5];
    const float* bv = (const float*)d_in[6];

    cudaFuncSetAttribute(qkv_mma, cudaFuncAttributeMaxDynamicSharedMemorySize, SMEM_DYN);

    convert_x<<<(ROWS * DD / 4) / 256, 256>>>(x);
    prep_w<<<520, 256>>>(Wq, bq, Wk, bk, Wv);
    qkv_mma<<<dim3(4, ROWS / 128, 2), 128, SMEM_DYN>>>(bv);
    score_out<<<TT * NN, 256>>>(x, (float*)d_out);
}

// round 14
// speedup vs baseline: 4.5412x; 1.0079x over previous
#include <cuda_runtime.h>
#include <cuda_bf16.h>
#include <cstdint>

// Problem dims
#define BB 4
#define TT 64
#define NN 16
#define MM 8
#define DD 512
#define ROWS (BB * TT * NN * MM)   // 32768 flattened (b,t,n,m) rows
#define TNM  (TT * NN * MM)

// ---------------------------------------------------------------------------
// Scratch (__device__ globals; allocation-free rule)
// ---------------------------------------------------------------------------
__device__ float g_Z[(size_t)ROWS * DD];     // Z = x * (Wq^T Wk)
__device__ float g_V[(size_t)ROWS * DD];
__device__ float g_W[TT * NN * MM * MM];     // softmax weights
__device__ float g_u[DD];                    // Wq^T bk
__device__ float g_v[DD];                    // Wk^T bq
__device__ float g_c;                        // bq . bk

__device__ __align__(16) __nv_bfloat16 g_xh[(size_t)ROWS * DD];
__device__ __align__(16) __nv_bfloat16 g_xl[(size_t)ROWS * DD];
__device__ __align__(16) __nv_bfloat16 g_wh[2 * DD * DD];   // z=0: Gt, z=1: Wv
__device__ __align__(16) __nv_bfloat16 g_wl[2 * DD * DD];

// ---------------------------------------------------------------------------
// Helpers
// ---------------------------------------------------------------------------
__device__ __forceinline__ uint32_t smem_to_u32(const void* smem_ptr) {
    uint32_t addr;
    asm("{ .reg .u64 tmp; cvta.to.shared.u64 tmp, %1; cvt.u32.u64 %0, tmp; }"
        : "=r"(addr) : "l"(smem_ptr));
    return addr;
}

#define SMEM_SWIZZLE_128B(byte_offset) \
    ((byte_offset) ^ (((byte_offset) >> 3) & 0x70))

__device__ __forceinline__ void cp_async16(uint32_t dst, const void* src) {
    asm volatile("cp.async.cg.shared.global [%0], [%1], 16;"
                 :: "r"(dst), "l"(src) : "memory");
}
__device__ __forceinline__ void cp_commit() {
    asm volatile("cp.async.commit_group;" ::: "memory");
}
__device__ __forceinline__ void cp_wait1() {
    asm volatile("cp.async.wait_group 1;" ::: "memory");
}
__device__ __forceinline__ void cp_wait0() {
    asm volatile("cp.async.wait_group 0;" ::: "memory");
}

__device__ __forceinline__ void ldmatrix_x4(
    uint32_t& r0, uint32_t& r1, uint32_t& r2, uint32_t& r3, uint32_t addr)
{
    asm volatile("ldmatrix.sync.aligned.m8n8.x4.shared.b16 {%0,%1,%2,%3}, [%4];"
                 : "=r"(r0), "=r"(r1), "=r"(r2), "=r"(r3) : "r"(addr));
}

__device__ __forceinline__ void mma_16816(
    float& c0, float& c1, float& c2, float& c3,
    uint32_t a0, uint32_t a1, uint32_t a2, uint32_t a3,
    uint32_t b0, uint32_t b1)
{
    asm volatile(
        "mma.sync.aligned.m16n8k16.row.col.f32.bf16.bf16.f32 "
        "{%0,%1,%2,%3}, {%4,%5,%6,%7}, {%8,%9}, {%0,%1,%2,%3};"
        : "+f"(c0), "+f"(c1), "+f"(c2), "+f"(c3)
        : "r"(a0), "r"(a1), "r"(a2), "r"(a3), "r"(b0), "r"(b1));
}

__device__ __forceinline__ uint32_t pack_bf16x2(__nv_bfloat16 a, __nv_bfloat16 b) {
    return (uint32_t)__bfloat16_as_ushort(a) | ((uint32_t)__bfloat16_as_ushort(b) << 16);
}

// ---------------------------------------------------------------------------
// Convert x: fp32 -> bf16 hi/lo split
// ---------------------------------------------------------------------------
__global__ __launch_bounds__(256) void convert_x(const float* __restrict__ x)
{
    size_t i = (size_t)blockIdx.x * 256 + threadIdx.x;
    float4 v = ((const float4*)x)[i];
    __nv_bfloat16 h0 = __float2bfloat16_rn(v.x);
    __nv_bfloat16 h1 = __float2bfloat16_rn(v.y);
    __nv_bfloat16 h2 = __float2bfloat16_rn(v.z);
    __nv_bfloat16 h3 = __float2bfloat16_rn(v.w);
    __nv_bfloat16 l0 = __float2bfloat16_rn(v.x - __bfloat162float(h0));
    __nv_bfloat16 l1 = __float2bfloat16_rn(v.y - __bfloat162float(h1));
    __nv_bfloat16 l2 = __float2bfloat16_rn(v.z - __bfloat162float(h2));
    __nv_bfloat16 l3 = __float2bfloat16_rn(v.w - __bfloat162float(h3));
    ((uint2*)g_xh)[i] = make_uint2(pack_bf16x2(h0, h1), pack_bf16x2(h2, h3));
    ((uint2*)g_xl)[i] = make_uint2(pack_bf16x2(l0, l1), pack_bf16x2(l2, l3));
}

// ---------------------------------------------------------------------------
// prep_w: fused weight prework, one launch, 520 blocks x 256 threads.
//   blocks [0,256):   Gt[j,i] = sum_e Wk[e,j]*Wq[e,i] -> bf16 hi/lo slot 0
//   blocks [256,512): convert Wv -> bf16 hi/lo slot 1
//   blocks [512,520): u/v/c bias precompute
// ---------------------------------------------------------------------------
__global__ __launch_bounds__(256) void prep_w(
    const float* __restrict__ Wq, const float* __restrict__ bq,
    const float* __restrict__ Wk, const float* __restrict__ bk,
    const float* __restrict__ Wv)
{
    __shared__ float Ak[16][36];
    __shared__ float Bk[16][36];
    __shared__ float su[4][64];
    __shared__ float sv[4][64];
    __shared__ float scc[64];

    const int bx  = blockIdx.x;
    const int tid = threadIdx.x;

    if (bx < 256) {
        // --- gemm_G: 32x32 tile, 2x2 microtile ---
        const int j0 = (bx >> 4) * 32;
        const int i0 = (bx & 15) * 32;
        const int le = tid >> 4;
        const int lc = (tid & 15) * 2;
        const int ty = tid >> 4;
        const int tx = tid & 15;

        float acc[2][2] = {{0.0f, 0.0f}, {0.0f, 0.0f}};

        for (int e0 = 0; e0 < DD; e0 += 16) {
            __syncthreads();
            *(float2*)&Ak[le][lc] = *(const float2*)(Wk + (size_t)(e0 + le) * DD + j0 + lc);
            *(float2*)&Bk[le][lc] = *(const float2*)(Wq + (size_t)(e0 + le) * DD + i0 + lc);
            __syncthreads();
#pragma unroll
            for (int e = 0; e < 16; e++) {
                float a0 = Ak[e][ty * 2], a1 = Ak[e][ty * 2 + 1];
                float b0 = Bk[e][tx * 2], b1 = Bk[e][tx * 2 + 1];
                acc[0][0] = fmaf(a0, b0, acc[0][0]);
                acc[0][1] = fmaf(a0, b1, acc[0][1]);
                acc[1][0] = fmaf(a1, b0, acc[1][0]);
                acc[1][1] = fmaf(a1, b1, acc[1][1]);
            }
        }

#pragma unroll
        for (int a = 0; a < 2; a++) {
            const int j = j0 + ty * 2 + a;
            const size_t off = (size_t)j * DD + i0 + tx * 2;
            __nv_bfloat16 h0 = __float2bfloat16_rn(acc[a][0]);
            __nv_bfloat16 h1 = __float2bfloat16_rn(acc[a][1]);
            __nv_bfloat16 l0 = __float2bfloat16_rn(acc[a][0] - __bfloat162float(h0));
            __nv_bfloat16 l1 = __float2bfloat16_rn(acc[a][1] - __bfloat162float(h1));
            *(uint32_t*)(g_wh + off) = pack_bf16x2(h0, h1);
            *(uint32_t*)(g_wl + off) = pack_bf16x2(l0, l1);
        }
    } else if (bx < 512) {
        // --- convert Wv into slot 1 ---
        size_t base = (size_t)(DD * DD / 4);
        size_t i = (size_t)(bx - 256) * 256 + tid;
        float4 v = ((const float4*)Wv)[i];
        __nv_bfloat16 h0 = __float2bfloat16_rn(v.x);
        __nv_bfloat16 h1 = __float2bfloat16_rn(v.y);
        __nv_bfloat16 h2 = __float2bfloat16_rn(v.z);
        __nv_bfloat16 h3 = __float2bfloat16_rn(v.w);
        __nv_bfloat16 l0 = __float2bfloat16_rn(v.x - __bfloat162float(h0));
        __nv_bfloat16 l1 = __float2bfloat16_rn(v.y - __bfloat162float(h1));
        __nv_bfloat16 l2 = __float2bfloat16_rn(v.z - __bfloat162float(h2));
        __nv_bfloat16 l3 = __float2bfloat16_rn(v.w - __bfloat162float(h3));
        ((uint2*)g_wh)[base + i] = make_uint2(pack_bf16x2(h0, h1), pack_bf16x2(h2, h3));
        ((uint2*)g_wl)[base + i] = make_uint2(pack_bf16x2(l0, l1), pack_bf16x2(l2, l3));
    } else {
        // --- bias u/v/c: 8 blocks of (64 i-lanes x 4 e-chunks) ---
        const int blk = bx - 512;
        const int il  = tid & 63;
        const int ec  = tid >> 6;
        const int i   = blk * 64 + il;

        float u = 0.0f, v = 0.0f;
        const int e0 = ec * 128;
#pragma unroll 4
        for (int e = e0; e < e0 + 128; e++) {
            u = fmaf(Wq[(size_t)e * DD + i], bk[e], u);
            v = fmaf(Wk[(size_t)e * DD + i], bq[e], v);
        }
        su[ec][il] = u;
        sv[ec][il] = v;
        __syncthreads();

        if (ec == 0) {
            g_u[i] = su[0][il] + su[1][il] + su[2][il] + su[3][il];
            g_v[i] = sv[0][il] + sv[1][il] + sv[2][il] + sv[3][il];
        }

        if (blk == 0) {
            if (ec == 1) {
                float s = 0.0f;
                for (int j = il; j < DD; j += 64) s = fmaf(bq[j], bk[j], s);
                scc[il] = s;
            }
            __syncthreads();
            if (ec == 0 && il == 0) {
                float s = 0.0f;
#pragma unroll
                for (int j = 0; j < 64; j++) s += scc[j];
                g_c = s;
            }
        }
    }
}

// ---------------------------------------------------------------------------
// Z/V GEMM via mma.sync bf16 (split-fp32), R7 shape + single-sync pipeline.
// z=0: Z = x*Gt^T (no bias); z=1: V = x*Wv^T + bv.
// CTA 128x128, 4 warps (2m x 2n), warp tile 64x64, 3-stage cp.async.
// grid = (4 n-tiles, 256 m-tiles, 2), 128 threads.
// ---------------------------------------------------------------------------
#define STAGE_BYTES 32768u   // A 16KB + B 16KB
#define SMEM_DYN (3 * STAGE_BYTES + 1024)

__global__ __launch_bounds__(128, 1) void qkv_mma(const float* __restrict__ bv)
{
    extern __shared__ __align__(16) char dsm[];
    const uint32_t raw  = smem_to_u32(dsm);
    const uint32_t base = (raw + 1023u) & ~1023u;

    const int tid  = threadIdx.x;
    const int wid  = tid >> 5;
    const int lane = tid & 31;
    const int wm   = wid & 1;
    const int wn   = wid >> 1;
    const int gid  = lane >> 2;
    const int tig  = lane & 3;

    const int z    = blockIdx.z;       // 0: Z, 1: V
    const int row0 = blockIdx.y * 128;
    const int col0 = blockIdx.x * 128;

    const __nv_bfloat16* whz = g_wh + (size_t)z * (DD * DD);
    const __nv_bfloat16* wlz = g_wl + (size_t)z * (DD * DD);

    uint32_t aAddr[4];
#pragma unroll
    for (int mf = 0; mf < 4; mf++) {
        int r = wm * 64 + mf * 16 + (lane & 15);
        uint32_t t = (uint32_t)((lane >> 4) * 16);
        aAddr[mf] = base + r * 128 + (t ^ ((uint32_t)(r & 7) * 16));
    }
    uint32_t bAddr[4];
#pragma unroll
    for (int bh = 0; bh < 4; bh++) {
        int n = wn * 64 + bh * 16 + (lane & 7) + ((lane >> 4) & 1) * 8;
        uint32_t t = (uint32_t)(((lane >> 3) & 1) * 16);
        bAddr[bh] = base + 16384u + n * 128 + (t ^ ((uint32_t)(n & 7) * 16));
    }

    float c[4][8][4];
#pragma unroll
    for (int mf = 0; mf < 4; mf++)
#pragma unroll
        for (int nf = 0; nf < 8; nf++)
#pragma unroll
            for (int q = 0; q < 4; q++) c[mf][nf][q] = 0.0f;

    auto issue_chunk = [&](int ci, int s) {
        const __nv_bfloat16* Asrc = (ci < 16) ? g_xh : g_xl;
        const __nv_bfloat16* Bsrc = (ci >= 8 && ci < 16) ? wlz : whz;
        const int koff = (ci & 7) * 64;
        const uint32_t stage = base + (uint32_t)s * STAGE_BYTES;
#pragma unroll
        for (int j = 0; j < 8; j++) {
            int idx = tid + j * 128;
            int r = idx >> 3, o = idx & 7;
            uint32_t bo = (uint32_t)(r * 128 + o * 16);
            cp_async16(stage + SMEM_SWIZZLE_128B(bo),
                       Asrc + (size_t)(row0 + r) * DD + koff + o * 8);
        }
#pragma unroll
        for (int j = 0; j < 8; j++) {
            int idx = tid + j * 128;
            int n = idx >> 3, o = idx & 7;
            uint32_t bo = (uint32_t)(n * 128 + o * 16);
            cp_async16(stage + 16384u + SMEM_SWIZZLE_128B(bo),
                       Bsrc + (size_t)(col0 + n) * DD + koff + o * 8);
        }
        cp_commit();
    };

    issue_chunk(0, 0);
    issue_chunk(1, 1);

    for (int ck = 0; ck < 24; ck++) {
        if (ck < 23) cp_wait1(); else cp_wait0();
        __syncthreads();
        if (ck + 2 < 24) issue_chunk(ck + 2, (ck + 2) % 3);

        const uint32_t soff = (uint32_t)(ck % 3) * STAGE_BYTES;
#pragma unroll
        for (int kk = 0; kk < 4; kk++) {
            const uint32_t kx = (uint32_t)(kk << 5);
            uint32_t a[4][4];
#pragma unroll
            for (int mf = 0; mf < 4; mf++)
                ldmatrix_x4(a[mf][0], a[mf][1], a[mf][2], a[mf][3],
                            (aAddr[mf] + soff) ^ kx);
            uint32_t b[8][2];
#pragma unroll
            for (int bh = 0; bh < 4; bh++) {
                uint32_t r0, r1, r2, r3;
                ldmatrix_x4(r0, r1, r2, r3, (bAddr[bh] + soff) ^ kx);
                b[bh * 2 + 0][0] = r0; b[bh * 2 + 0][1] = r1;
                b[bh * 2 + 1][0] = r2; b[bh * 2 + 1][1] = r3;
            }
#pragma unroll
            for (int mf = 0; mf < 4; mf++)
#pragma unroll
                for (int nf = 0; nf < 8; nf++)
                    mma_16816(c[mf][nf][0], c[mf][nf][1], c[mf][nf][2], c[mf][nf][3],
                              a[mf][0], a[mf][1], a[mf][2], a[mf][3],
                              b[nf][0], b[nf][1]);
        }
    }

    float* out = (z == 0) ? g_Z : g_V;

#pragma unroll
    for (int nf = 0; nf < 8; nf++) {
        const int col = col0 + wn * 64 + nf * 8 + tig * 2;
        float2 bb = (z == 1) ? *(const float2*)(bv + col) : make_float2(0.0f, 0.0f);
#pragma unroll
        for (int mf = 0; mf < 4; mf++) {
            const int r0 = row0 + wm * 64 + mf * 16 + gid;
            float2 v0 = make_float2(c[mf][nf][0] + bb.x, c[mf][nf][1] + bb.y);
            float2 v1 = make_float2(c[mf][nf][2] + bb.x, c[mf][nf][3] + bb.y);
            *(float2*)(out + (size_t)r0 * DD + col)       = v0;
            *(float2*)(out + (size_t)(r0 + 8) * DD + col) = v1;
        }
    }
}

// ---------------------------------------------------------------------------
// score_softmax: scores + softmax -> g_W.
// score[m,k] = (Sum_b Sum_d Z[b,m,d]*x[b,k,d] + P[m] + R[k] + 4c) * scale
// One block per (t,n), 256 threads; parallel 256-thread partial reduction.
// ---------------------------------------------------------------------------
__global__ __launch_bounds__(256) void score_softmax(const float* __restrict__ x)
{
    __shared__ float sQ[4096];        // Z rows   [4b][8][128]
    __shared__ float sK[4096];        // x rows   [4b][8][128]
    __shared__ float part[64 * 65];
    __shared__ float red[4][64];
    __shared__ float Pp[4][8][9];
    __shared__ float Rp[4][8][9];
    __shared__ float PP[8], RR[8];
    __shared__ float sc[64];
    __shared__ float es[64];

    const int tn  = blockIdx.x;
    const int tid = threadIdx.x;
    const int b    = tid >> 6;
    const int r    = tid & 63;
    const int tile = r >> 4;
    const int slc  = r & 15;
    const int mt   = tile >> 1;
    const int kt   = tile & 1;

    const int pb   = tid >> 6;
    const int prow = (tid >> 3) & 7;
    const int ps8  = tid & 7;

    float acc[4][4];
#pragma unroll
    for (int i = 0; i < 4; i++)
#pragma unroll
        for (int j = 0; j < 4; j++) acc[i][j] = 0.0f;
    float pr = 0.0f, rr = 0.0f;

    const float4* Z4 = (const float4*)g_Z;
    const float4* X4 = (const float4*)x;
    const float4* u4 = (const float4*)g_u;
    const float4* v4 = (const float4*)g_v;

    for (int ch = 0; ch < 4; ch++) {
        __syncthreads();
#pragma unroll
        for (int j = 0; j < 4; j++) {
            int idx = tid + j * 256;
            int lb = idx >> 8, lrr = (idx >> 5) & 7, o = idx & 31;
            size_t grow = (size_t)lb * TNM + (size_t)tn * MM + lrr;
            ((float4*)sQ)[(lb * 8 + lrr) * 32 + o] = Z4[grow * (DD / 4) + ch * 32 + o];
            ((float4*)sK)[(lb * 8 + lrr) * 32 + o] = X4[grow * (DD / 4) + ch * 32 + o];
        }
        __syncthreads();

#pragma unroll
        for (int j = 0; j < 2; j++) {
            const int d4 = j * 16 + slc;
            float4 qf[4], kf[4];
#pragma unroll
            for (int i = 0; i < 4; i++)
                qf[i] = ((const float4*)sQ)[(b * 8 + mt * 4 + i) * 32 + d4];
#pragma unroll
            for (int i = 0; i < 4; i++)
                kf[i] = ((const float4*)sK)[(b * 8 + kt * 4 + i) * 32 + d4];
#pragma unroll
            for (int i = 0; i < 4; i++)
#pragma unroll
                for (int kx = 0; kx < 4; kx++) {
                    acc[i][kx] = fmaf(qf[i].x, kf[kx].x, acc[i][kx]);
                    acc[i][kx] = fmaf(qf[i].y, kf[kx].y, acc[i][kx]);
                    acc[i][kx] = fmaf(qf[i].z, kf[kx].z, acc[i][kx]);
                    acc[i][kx] = fmaf(qf[i].w, kf[kx].w, acc[i][kx]);
                }
        }

#pragma unroll
        for (int ww = 0; ww < 4; ww++) {
            float4 xv = ((const float4*)sK)[(pb * 8 + prow) * 32 + ps8 * 4 + ww];
            float4 uu = u4[ch * 32 + ps8 * 4 + ww];
            float4 vv = v4[ch * 32 + ps8 * 4 + ww];
            pr = fmaf(xv.x, uu.x, pr); pr = fmaf(xv.y, uu.y, pr);
            pr = fmaf(xv.z, uu.z, pr); pr = fmaf(xv.w, uu.w, pr);
            rr = fmaf(xv.x, vv.x, rr); rr = fmaf(xv.y, vv.y, rr);
            rr = fmaf(xv.z, vv.z, rr); rr = fmaf(xv.w, vv.w, rr);
        }
    }

    const int h = b * 16 + slc;
#pragma unroll
    for (int i = 0; i < 4; i++)
#pragma unroll
        for (int kx = 0; kx < 4; kx++) {
            int pair = (mt * 4 + i) * 8 + (kt * 4 + kx);
            part[h * 65 + pair] = acc[i][kx];
        }
    Pp[pb][prow][ps8] = pr;
    Rp[pb][prow][ps8] = rr;
    __syncthreads();

    // Parallel partial reduction: 256 threads, each sums 16 of 64 h-slices.
    {
        const int pair = tid & 63;
        const int q    = tid >> 6;
        float s = 0.0f;
#pragma unroll
        for (int hh = q * 16; hh < q * 16 + 16; hh++) s += part[hh * 65 + pair];
        red[q][pair] = s;
    }
    if (tid < 8) {
        float s = 0.0f;
#pragma unroll
        for (int bb = 0; bb < 4; bb++)
#pragma unroll
            for (int ss = 0; ss < 8; ss++) s += Pp[bb][tid][ss];
        PP[tid] = s;
    } else if (tid < 16) {
        const int m = tid - 8;
        float s = 0.0f;
#pragma unroll
        for (int bb = 0; bb < 4; bb++)
#pragma unroll
            for (int ss = 0; ss < 8; ss++) s += Rp[bb][m][ss];
        RR[m] = s;
    }
    __syncthreads();

    if (tid < 64) {
        float s = red[0][tid] + red[1][tid] + red[2][tid] + red[3][tid];
        const int m = tid >> 3, k = tid & 7;
        sc[tid] = (s + PP[m] + RR[k] + 4.0f * g_c) * 0.04419417382415922f;
    }
    __syncthreads();

    if (tid < 64) {
        const int m = tid >> 3;
        float mx = sc[m * 8];
#pragma unroll
        for (int j = 1; j < 8; j++) mx = fmaxf(mx, sc[m * 8 + j]);
        es[tid] = expf(sc[tid] - mx);
    }
    __syncthreads();

    if (tid < 64) {
        const int m = tid >> 3;
        float sum = 0.0f;
#pragma unroll
        for (int j = 0; j < 8; j++) sum += es[m * 8 + j];
        g_W[tn * 64 + tid] = es[tid] / sum;
    }
}

// ---------------------------------------------------------------------------
// out_kernel: out[b,t,n,m,:] = sum_k w[m,k] * V[b,t,n,k,:]
// One block per (b,t,n), 4096 blocks, 256 threads.
// ---------------------------------------------------------------------------
__global__ __launch_bounds__(256) void out_kernel(float* __restrict__ out)
{
    const int btn = blockIdx.x;
    const int tid = threadIdx.x;
    const int d4  = tid & 127;
    const int mh  = tid >> 7;
    const int tn  = btn % (TT * NN);

    __shared__ float w[64];
    if (tid < 64) w[tid] = g_W[tn * 64 + tid];
    __syncthreads();

    const float4* V4 = (const float4*)(g_V + (size_t)btn * MM * DD);
    float4* O4 = (float4*)(out + (size_t)btn * MM * DD);

    float4 acc[4];
#pragma unroll
    for (int i = 0; i < 4; i++) acc[i] = make_float4(0.f, 0.f, 0.f, 0.f);

#pragma unroll
    for (int k = 0; k < 8; k++) {
        float4 v = V4[k * (DD / 4) + d4];
#pragma unroll
        for (int i = 0; i < 4; i++) {
            float wm = w[(mh * 4 + i) * 8 + k];
            acc[i].x = fmaf(wm, v.x, acc[i].x);
            acc[i].y = fmaf(wm, v.y, acc[i].y);
            acc[i].z = fmaf(wm, v.z, acc[i].z);
            acc[i].w = fmaf(wm, v.w, acc[i].w);
        }
    }

#pragma unroll
    for (int i = 0; i < 4; i++) {
        O4[(mh * 4 + i) * (DD / 4) + d4] = acc[i];
    }
}

// ---------------------------------------------------------------------------
extern "C" void kernel_launch(void* const* d_in, const int* in_sizes, int n_in,
                              void* d_out, int out_size)
{
    const float* x  = (const float*)d_in[0];
    const float* Wq = (const float*)d_in[1];
    const float* bq = (const float*)d_in[2];
    const float* Wk = (const float*)d_in[3];
    const float* bk = (const float*)d_in[4];
    const float* Wv = (const float*)d_in[5];
    const float* bv = (const float*)d_in[6];

    cudaFuncSetAttribute(qkv_mma, cudaFuncAttributeMaxDynamicSharedMemorySize, SMEM_DYN);

    convert_x<<<(ROWS * DD / 4) / 256, 256>>>(x);
    prep_w<<<520, 256>>>(Wq, bq, Wk, bk, Wv);
    qkv_mma<<<dim3(4, ROWS / 128, 2), 128, SMEM_DYN>>>(bv);
    score_softmax<<<TT * NN, 256>>>(x);
    out_kernel<<<BB * TT * NN, 256>>>((float*)d_out);
}